// round 7
// baseline (speedup 1.0000x reference)
#include <cuda_runtime.h>
#include <cuda_bf16.h>
#include <cuda_fp8.h>
#include <stdint.h>

// Problem constants
#define Bq   4
#define Tq   2048
#define Dq   1024
#define Hq   16
#define HDq  64
#define Mq   (Bq * Tq)        // 8192
#define DFF  (4 * Dq)         // 4096
#define LN_EPS 1e-5f
#define ATT_SCALE 0.125f
#define LOSCALE 256.0f
#define INV_LOSCALE (1.0f / 256.0f)

// ---------------------------------------------------------------------------
// Scratch
// ---------------------------------------------------------------------------
__device__ __nv_bfloat16 g_h_hi[Mq * Dq];
__device__ uint8_t       g_h8[Mq * 2 * Dq];
__device__ __nv_bfloat16 g_wqkv_hi[3*Dq*Dq];
__device__ uint8_t       g_wqkv8[3*Dq * 2*Dq];
__device__ __nv_bfloat16 g_wp_hi[Dq*Dq];
__device__ uint8_t       g_wp8[Dq * 2*Dq];
__device__ __nv_bfloat16 g_w1_hi[DFF*Dq];
__device__ uint8_t       g_w18[DFF * 2*Dq];
__device__ __nv_bfloat16 g_w2_hi[Dq*DFF];
__device__ uint8_t       g_w28[Dq * 2*DFF];
__device__ __nv_bfloat16 g_qkvh[Mq * 3 * Dq], g_qkvl[Mq * 3 * Dq];  // q pre-scaled
__device__ __nv_bfloat16 g_attn_hi[Mq * Dq];
__device__ uint8_t       g_attn8[Mq * 2 * Dq];
__device__ float         g_x1[Mq * Dq];
__device__ __nv_bfloat16 g_ff_hi[Mq * DFF];
__device__ uint8_t       g_ff8[Mq * 2 * DFF];

// ---------------------------------------------------------------------------
// Helpers
// ---------------------------------------------------------------------------
__device__ __forceinline__ uint8_t to_e4m3(float v) {
    return (uint8_t)__nv_cvt_float_to_fp8(v, __NV_SATFINITE, __NV_E4M3);
}

__device__ __forceinline__ void split_bf16(float v, __nv_bfloat16& hi, __nv_bfloat16& lo) {
    hi = __float2bfloat16(v);
    lo = __float2bfloat16(v - __bfloat162float(hi));
}

__device__ __forceinline__ uint32_t pack2(float x, float y, uint32_t& lo) {
    __nv_bfloat16 hx = __float2bfloat16(x), hy = __float2bfloat16(y);
    __nv_bfloat16 lx = __float2bfloat16(x - __bfloat162float(hx));
    __nv_bfloat16 ly = __float2bfloat16(y - __bfloat162float(hy));
    __nv_bfloat162 h2(hx, hy), l2(lx, ly);
    lo = *reinterpret_cast<uint32_t*>(&l2);
    return *reinterpret_cast<uint32_t*>(&h2);
}

__device__ __forceinline__ void mma16816(float* c, const uint32_t* a, const uint32_t* b) {
    asm volatile(
        "mma.sync.aligned.m16n8k16.row.col.f32.bf16.bf16.f32 "
        "{%0,%1,%2,%3}, {%4,%5,%6,%7}, {%8,%9}, {%0,%1,%2,%3};"
        : "+f"(c[0]), "+f"(c[1]), "+f"(c[2]), "+f"(c[3])
        : "r"(a[0]), "r"(a[1]), "r"(a[2]), "r"(a[3]), "r"(b[0]), "r"(b[1]));
}

__device__ __forceinline__ void mma_fp8(float* c, const uint32_t* a, const uint32_t* b) {
    asm volatile(
        "mma.sync.aligned.m16n8k32.row.col.f32.e4m3.e4m3.f32 "
        "{%0,%1,%2,%3}, {%4,%5,%6,%7}, {%8,%9}, {%0,%1,%2,%3};"
        : "+f"(c[0]), "+f"(c[1]), "+f"(c[2]), "+f"(c[3])
        : "r"(a[0]), "r"(a[1]), "r"(a[2]), "r"(a[3]), "r"(b[0]), "r"(b[1]));
}

__device__ __forceinline__ void ldmx4(uint32_t* r, const void* p) {
    uint32_t a = (uint32_t)__cvta_generic_to_shared(p);
    asm volatile("ldmatrix.sync.aligned.m8n8.x4.shared.b16 {%0,%1,%2,%3}, [%4];"
                 : "=r"(r[0]), "=r"(r[1]), "=r"(r[2]), "=r"(r[3]) : "r"(a));
}

__device__ __forceinline__ void ldmx2t(uint32_t& r0, uint32_t& r1, const void* p) {
    uint32_t a = (uint32_t)__cvta_generic_to_shared(p);
    asm volatile("ldmatrix.sync.aligned.m8n8.x2.trans.shared.b16 {%0,%1}, [%2];"
                 : "=r"(r0), "=r"(r1) : "r"(a));
}

__device__ __forceinline__ void cp16(void* sdst, const void* gsrc) {
    unsigned sa = (unsigned)__cvta_generic_to_shared(sdst);
    asm volatile("cp.async.cg.shared.global [%0], [%1], 16;" :: "r"(sa), "l"(gsrc));
}
#define CP_COMMIT() asm volatile("cp.async.commit_group;")
#define CP_WAIT0()  asm volatile("cp.async.wait_group 0;")
#define CP_WAIT1()  asm volatile("cp.async.wait_group 1;")

// ---------------------------------------------------------------------------
// Weight prep: tiled transpose + split (bf16 hi + fp8 concat [N][2K])
// ---------------------------------------------------------------------------
__global__ void prep_wqkv_tiled(const float* __restrict__ Wq,
                                const float* __restrict__ Wk,
                                const float* __restrict__ Wv,
                                __nv_bfloat16* __restrict__ o_hi,
                                uint8_t* __restrict__ o8)
{
    __shared__ float t[32][33];
    int s = blockIdx.z >> 4, h = blockIdx.z & 15;
    const float* W = (s == 0) ? Wq : (s == 1) ? Wk : Wv;
    const float* in = W + (long)h * Dq * HDq;
    int d0 = blockIdx.y * 32, hd0 = blockIdx.x * 32;
    int tx = threadIdx.x, ty = threadIdx.y;
    #pragma unroll
    for (int i = 0; i < 32; i += 8)
        t[ty + i][tx] = in[(long)(d0 + ty + i) * HDq + hd0 + tx];
    __syncthreads();
    long nrow = (long)s * Dq + h * HDq + hd0;
    #pragma unroll
    for (int i = 0; i < 32; i += 8) {
        float v = t[tx][ty + i];
        long n = nrow + ty + i;
        long k = d0 + tx;
        __nv_bfloat16 hb, lb;
        split_bf16(v, hb, lb);
        o_hi[n * Dq + k] = hb;
        o8[n * 2 * Dq + k]      = to_e4m3(__bfloat162float(hb));               // Bhi region
        o8[n * 2 * Dq + Dq + k] = to_e4m3(__bfloat162float(lb) * LOSCALE);     // Blo*256 region
    }
}

// in: [K][N] fp32 -> out: hi bf16 [N][K] + fp8 concat [N][2K]
__global__ void transpose_split8(const float* __restrict__ in,
                                 __nv_bfloat16* __restrict__ o_hi,
                                 uint8_t* __restrict__ o8,
                                 int K, int N)
{
    __shared__ float t[32][33];
    int k0 = blockIdx.y * 32, n0 = blockIdx.x * 32;
    int tx = threadIdx.x, ty = threadIdx.y;
    #pragma unroll
    for (int i = 0; i < 32; i += 8)
        t[ty + i][tx] = in[(long)(k0 + ty + i) * N + n0 + tx];
    __syncthreads();
    #pragma unroll
    for (int i = 0; i < 32; i += 8) {
        float v = t[tx][ty + i];
        long n = n0 + ty + i;
        long k = k0 + tx;
        __nv_bfloat16 hb, lb;
        split_bf16(v, hb, lb);
        o_hi[n * K + k] = hb;
        o8[n * 2L * K + k]     = to_e4m3(__bfloat162float(hb));
        o8[n * 2L * K + K + k] = to_e4m3(__bfloat162float(lb) * LOSCALE);
    }
}

// ---------------------------------------------------------------------------
// LayerNorm -> hi bf16 + fp8 activation concat [M][2K]  (A' = [lo*256 | hi])
// ---------------------------------------------------------------------------
__global__ void ln_split8(const float* __restrict__ x,
                          const float* __restrict__ g,
                          const float* __restrict__ b,
                          __nv_bfloat16* __restrict__ o_hi,
                          uint8_t* __restrict__ o8)
{
    __shared__ float red[16];
    int row = blockIdx.x;
    int t = threadIdx.x;
    const float4* xr = (const float4*)(x + (long)row * Dq);
    float4 v = xr[t];
    float s  = v.x + v.y + v.z + v.w;
    float ss = v.x * v.x + v.y * v.y + v.z * v.z + v.w * v.w;
    #pragma unroll
    for (int o = 16; o >= 1; o >>= 1) {
        s  += __shfl_xor_sync(0xffffffffu, s,  o);
        ss += __shfl_xor_sync(0xffffffffu, ss, o);
    }
    if ((t & 31) == 0) { red[t >> 5] = s; red[8 + (t >> 5)] = ss; }
    __syncthreads();
    float stot = 0.f, sstot = 0.f;
    #pragma unroll
    for (int w = 0; w < 8; w++) { stot += red[w]; sstot += red[8 + w]; }
    float mu  = stot * (1.f / Dq);
    float var = sstot * (1.f / Dq) - mu * mu;
    float inv = rsqrtf(var + LN_EPS);
    float4 gg = ((const float4*)g)[t];
    float4 bb = ((const float4*)b)[t];
    float ov[4];
    ov[0] = (v.x - mu) * inv * gg.x + bb.x;
    ov[1] = (v.y - mu) * inv * gg.y + bb.y;
    ov[2] = (v.z - mu) * inv * gg.z + bb.z;
    ov[3] = (v.w - mu) * inv * gg.w + bb.w;
    uint32_t hiw[2], low = 0, hi8w = 0;
    __nv_bfloat16 hb[4];
    #pragma unroll
    for (int j = 0; j < 4; j++) {
        hb[j] = __float2bfloat16(ov[j]);
        float lo = ov[j] - __bfloat162float(hb[j]);
        low  |= (uint32_t)to_e4m3(lo * LOSCALE) << (8 * j);
        hi8w |= (uint32_t)to_e4m3(__bfloat162float(hb[j])) << (8 * j);
    }
    __nv_bfloat162 h01(hb[0], hb[1]), h23(hb[2], hb[3]);
    hiw[0] = *(uint32_t*)&h01; hiw[1] = *(uint32_t*)&h23;
    long base = (long)row * Dq + t * 4;
    *(uint32_t*)(o_hi + base)     = hiw[0];
    *(uint32_t*)(o_hi + base + 2) = hiw[1];
    *(uint32_t*)(o8 + (long)row * 2 * Dq + t * 4)      = low;    // lo*256 region
    *(uint32_t*)(o8 + (long)row * 2 * Dq + Dq + t * 4) = hi8w;   // hi region
}

// ---------------------------------------------------------------------------
// GEMM: C = A @ B  via bf16-hi main pass + fp8 K-concat correction pass.
// Tile 128x256, 8 warps (2x4), warp 64x64, 3-stage cp.async.
// Phase 0: fp8, A'=[Alo*256|Ahi], B'=[Bhi|Blo*256] over 2K; then acc *= 2^-8.
// Phase 1: bf16 Ahi*Bhi over K.
// EPI: 2 +bias+residual fp32; 3 +bias+relu -> hi bf16 + fp8 concat;
//      4 -> hi/lo bf16 with q prescale (QKV, feeds flash)
// ---------------------------------------------------------------------------
#define KPAD 40
#define A_ROWS 128
#define B_ROWS 256
#define AST (A_ROWS * KPAD)
#define BST (B_ROWS * KPAD)
#define STAGE_U (AST + BST)                 // 15360 b16 units
#define GEMM_SMEM (3 * STAGE_U * 2)         // 92160 B

template <int EPI>
__global__ void __launch_bounds__(256, 1)
gemm_hi8(const __nv_bfloat16* __restrict__ Ahi,
         const uint8_t* __restrict__ A8,
         const __nv_bfloat16* __restrict__ Bhi,
         const uint8_t* __restrict__ B8,
         const float* __restrict__ bias,
         const float* __restrict__ res,
         float* __restrict__ C,
         __nv_bfloat16* __restrict__ Chi,
         __nv_bfloat16* __restrict__ Clo,
         uint8_t* __restrict__ C8,
         int N, int K)
{
    extern __shared__ __nv_bfloat16 smem[];
    const int tid  = threadIdx.x;
    const int lane = tid & 31;
    const int warp = tid >> 5;
    const int wm = warp >> 2;
    const int wn = warp & 3;
    const int a_r = lane & 15;
    const int a_c = (lane >> 4) << 3;
    const int b_r = (lane & 7) + ((lane >> 4) << 3);
    const int b_c = ((lane >> 3) & 1) << 3;

    const int bm = blockIdx.y, bn = blockIdx.x;
    const long STRIDE = 2L * K;   // bytes per row for BOTH fp8 (2K) and bf16 (K*2)
    const uint8_t* A0 = A8 + (long)bm * 128 * STRIDE;
    const uint8_t* B0 = B8 + (long)bn * 256 * STRIDE;
    const uint8_t* A1 = (const uint8_t*)Ahi + (long)bm * 128 * STRIDE;
    const uint8_t* B1 = (const uint8_t*)Bhi + (long)bn * 256 * STRIDE;

    const int NIT = K / 32;   // per phase: 64 bytes of K-stride per iteration

    float acc[4][8][4];
    #pragma unroll
    for (int i = 0; i < 4; i++)
        #pragma unroll
        for (int j = 0; j < 8; j++)
            #pragma unroll
            for (int r = 0; r < 4; r++) acc[i][j][r] = 0.f;

    auto ld_stage = [&](int st, const uint8_t* As, const uint8_t* Bs, long kbyte) {
        uint8_t* SA = (uint8_t*)(smem + (size_t)st * STAGE_U);
        uint8_t* SB = SA + AST * 2;
        #pragma unroll
        for (int i = 0; i < 2; i++) {
            int c = tid + i * 256;
            int row = c >> 2, ch = (c & 3) * 16;
            cp16(SA + row * 80 + ch, As + (long)row * STRIDE + kbyte + ch);
        }
        #pragma unroll
        for (int i = 0; i < 4; i++) {
            int c = tid + i * 256;
            int row = c >> 2, ch = (c & 3) * 16;
            cp16(SB + row * 80 + ch, Bs + (long)row * STRIDE + kbyte + ch);
        }
    };

#define GEMM_PHASE(Asrc, Bsrc, MMAFN)                                          \
    do {                                                                       \
        ld_stage(0, Asrc, Bsrc, 0);  CP_COMMIT();                              \
        ld_stage(1, Asrc, Bsrc, 64); CP_COMMIT();                              \
        int st = 0;                                                            \
        for (int it = 0; it < NIT; it++) {                                     \
            if (it + 1 < NIT) { CP_WAIT1(); } else { CP_WAIT0(); }             \
            __syncthreads();                                                   \
            if (it + 2 < NIT) {                                                \
                int wst = st + 2; if (wst >= 3) wst -= 3;                      \
                ld_stage(wst, Asrc, Bsrc, (long)(it + 2) * 64);                \
                CP_COMMIT();                                                   \
            }                                                                  \
            const __nv_bfloat16* SAu = smem + (size_t)st * STAGE_U;            \
            const __nv_bfloat16* SBu = SAu + AST;                              \
            _Pragma("unroll")                                                  \
            for (int ks = 0; ks < 2; ks++) {                                   \
                const int k16 = ks * 16;                                       \
                uint32_t af[4][4], bf[8][2];                                   \
                _Pragma("unroll")                                              \
                for (int mt = 0; mt < 4; mt++)                                 \
                    ldmx4(af[mt], SAu + (wm * 64 + mt * 16 + a_r) * KPAD + k16 + a_c); \
                _Pragma("unroll")                                              \
                for (int np = 0; np < 4; np++) {                               \
                    uint32_t r[4];                                             \
                    ldmx4(r, SBu + (wn * 64 + np * 16 + b_r) * KPAD + k16 + b_c); \
                    bf[2*np][0] = r[0]; bf[2*np][1] = r[1];                    \
                    bf[2*np+1][0] = r[2]; bf[2*np+1][1] = r[3];                \
                }                                                              \
                _Pragma("unroll")                                              \
                for (int mt = 0; mt < 4; mt++)                                 \
                    _Pragma("unroll")                                          \
                    for (int nt = 0; nt < 8; nt++)                             \
                        MMAFN(acc[mt][nt], af[mt], bf[nt]);                    \
            }                                                                  \
            if (++st == 3) st = 0;                                             \
        }                                                                      \
        __syncthreads();                                                       \
    } while (0)

    // Phase 0: fp8 correction over 2K (result carries a 2^8 factor)
    GEMM_PHASE(A0, B0, mma_fp8);

    #pragma unroll
    for (int i = 0; i < 4; i++)
        #pragma unroll
        for (int j = 0; j < 8; j++)
            #pragma unroll
            for (int r = 0; r < 4; r++) acc[i][j][r] *= INV_LOSCALE;

    // Phase 1: bf16 main (hi*hi) over K
    GEMM_PHASE(A1, B1, mma16816);
#undef GEMM_PHASE

    // epilogue
    const int lr4 = lane >> 2;
    const int lc2 = (lane & 3) * 2;
    #pragma unroll
    for (int mt = 0; mt < 4; mt++) {
        #pragma unroll
        for (int nt = 0; nt < 8; nt++) {
            int c = bn * 256 + wn * 64 + nt * 8 + lc2;
            #pragma unroll
            for (int half = 0; half < 2; half++) {
                int r = bm * 128 + wm * 64 + mt * 16 + lr4 + half * 8;
                float v0 = acc[mt][nt][half * 2 + 0];
                float v1 = acc[mt][nt][half * 2 + 1];
                long off = (long)r * N + c;
                if (EPI == 2) {
                    float2 bv = *(const float2*)(bias + c);
                    float2 rv = *(const float2*)(res + off);
                    *(float2*)(C + off) = make_float2(v0 + bv.x + rv.x,
                                                      v1 + bv.y + rv.y);
                } else if (EPI == 3) {
                    float2 bv = *(const float2*)(bias + c);
                    v0 = fmaxf(v0 + bv.x, 0.f);
                    v1 = fmaxf(v1 + bv.y, 0.f);
                    __nv_bfloat16 h0 = __float2bfloat16(v0);
                    __nv_bfloat16 h1 = __float2bfloat16(v1);
                    __nv_bfloat162 hw(h0, h1);
                    *(uint32_t*)(Chi + off) = *(uint32_t*)&hw;
                    uint16_t l8 = (uint16_t)to_e4m3((v0 - __bfloat162float(h0)) * LOSCALE)
                                | ((uint16_t)to_e4m3((v1 - __bfloat162float(h1)) * LOSCALE) << 8);
                    uint16_t h8 = (uint16_t)to_e4m3(__bfloat162float(h0))
                                | ((uint16_t)to_e4m3(__bfloat162float(h1)) << 8);
                    *(uint16_t*)(C8 + (long)r * 2 * N + c)     = l8;
                    *(uint16_t*)(C8 + (long)r * 2 * N + N + c) = h8;
                } else {  // EPI == 4: split bf16 (hi/lo), q cols prescaled
                    float scale = (c < Dq) ? ATT_SCALE : 1.f;
                    uint32_t lo;
                    uint32_t hi = pack2(v0 * scale, v1 * scale, lo);
                    *(uint32_t*)(Chi + off) = hi;
                    *(uint32_t*)(Clo + off) = lo;
                }
            }
        }
    }
}

// ---------------------------------------------------------------------------
// Tensor-core flash attention (bf16x3, R6 version) — epilogue now emits
// hi bf16 + fp8 concat for the proj GEMM.
// ---------------------------------------------------------------------------
#define FPAD 72
#define FLASH_SMEM ((2 * 128 * FPAD + 2 * 4 * 64 * FPAD) * 2)

__global__ void __launch_bounds__(256)
flash_tc(const __nv_bfloat16* __restrict__ qkvh,
         const __nv_bfloat16* __restrict__ qkvl,
         __nv_bfloat16* __restrict__ out_hi,
         uint8_t* __restrict__ out8)
{
    extern __shared__ __nv_bfloat16 sm[];
    __nv_bfloat16* QH = sm;
    __nv_bfloat16* QL = sm + 128 * FPAD;

    const int qi  = gridDim.x - 1 - blockIdx.x;
    const int bh  = blockIdx.y;
    const int b   = bh >> 4;
    const int h   = bh & 15;
    const int tid  = threadIdx.x;
    const int lane = tid & 31;
    const int warp = tid >> 5;
    const int g  = lane >> 2;
    const int t2 = (lane & 3) * 2;
    const int a_r = lane & 15;
    const int a_c = (lane >> 4) << 3;
    const int b_r = (lane & 7) + ((lane >> 4) << 3);
    const int b_c = ((lane >> 3) & 1) << 3;

    const long rb = (long)b * Tq;
    const __nv_bfloat16* qh = qkvh + (rb + qi * 128) * (3 * Dq) + h * HDq;
    const __nv_bfloat16* ql = qkvl + (rb + qi * 128) * (3 * Dq) + h * HDq;
    const __nv_bfloat16* kh = qkvh + rb * (3 * Dq) + Dq + h * HDq;
    const __nv_bfloat16* kl = qkvl + rb * (3 * Dq) + Dq + h * HDq;
    const __nv_bfloat16* vh = qkvh + rb * (3 * Dq) + 2 * Dq + h * HDq;
    const __nv_bfloat16* vl = qkvl + rb * (3 * Dq) + 2 * Dq + h * HDq;

    auto kvbase = [&](int st) -> __nv_bfloat16* {
        return sm + 2 * 128 * FPAD + st * (4 * 64 * FPAD);
    };
    auto ldkv = [&](int st, int jt) {
        __nv_bfloat16* KB = kvbase(st);
        #pragma unroll
        for (int i = 0; i < 2; i++) {
            int c = tid + i * 256;
            int row = c >> 3;
            int c8 = (c & 7) * 8;
            long go = (long)(jt * 64 + row) * (3 * Dq) + c8;
            int so = row * FPAD + c8;
            cp16(KB + so,                 kh + go);
            cp16(KB + 64 * FPAD + so,     kl + go);
            cp16(KB + 2 * 64 * FPAD + so, vh + go);
            cp16(KB + 3 * 64 * FPAD + so, vl + go);
        }
    };

    #pragma unroll
    for (int i = 0; i < 4; i++) {
        int c = tid + i * 256;
        int row = c >> 3;
        int c8 = (c & 7) * 8;
        cp16(QH + row * FPAD + c8, qh + (long)row * (3 * Dq) + c8);
        cp16(QL + row * FPAD + c8, ql + (long)row * (3 * Dq) + c8);
    }
    ldkv(0, 0);
    CP_COMMIT();

    float oacc[8][4];
    #pragma unroll
    for (int nt = 0; nt < 8; nt++)
        #pragma unroll
        for (int e = 0; e < 4; e++) oacc[nt][e] = 0.f;
    float m0 = -1e30f, m1 = -1e30f, l0 = 0.f, l1 = 0.f;

    uint32_t qfh[4][4], qfl[4][4];
    const int qrow0 = qi * 128 + warp * 16 + g;
    const int jmax = 2 * qi + 1;

    for (int jt = 0; jt <= jmax; jt++) {
        CP_WAIT0();
        __syncthreads();
        if (jt < jmax) { ldkv((jt + 1) & 1, jt + 1); CP_COMMIT(); }

        if (jt == 0) {
            #pragma unroll
            for (int kt = 0; kt < 4; kt++) {
                int row = warp * 16 + a_r;
                ldmx4(qfh[kt], QH + row * FPAD + kt * 16 + a_c);
                ldmx4(qfl[kt], QL + row * FPAD + kt * 16 + a_c);
            }
        }

        if (jt * 64 <= qi * 128 + warp * 16 + 15) {
            __nv_bfloat16* KB = kvbase(jt & 1);
            const __nv_bfloat16* KHs = KB;
            const __nv_bfloat16* KLs = KB + 64 * FPAD;
            const __nv_bfloat16* VHs = KB + 2 * 64 * FPAD;
            const __nv_bfloat16* VLs = KB + 3 * 64 * FPAD;

            float sacc[8][4];
            #pragma unroll
            for (int nt = 0; nt < 8; nt++)
                #pragma unroll
                for (int e = 0; e < 4; e++) sacc[nt][e] = 0.f;

            #pragma unroll
            for (int kt = 0; kt < 4; kt++) {
                uint32_t bh2[8][2], bl2[8][2];
                #pragma unroll
                for (int np = 0; np < 4; np++) {
                    int row = np * 16 + b_r;
                    uint32_t r[4];
                    ldmx4(r, KHs + row * FPAD + kt * 16 + b_c);
                    bh2[2*np][0] = r[0]; bh2[2*np][1] = r[1];
                    bh2[2*np+1][0] = r[2]; bh2[2*np+1][1] = r[3];
                    ldmx4(r, KLs + row * FPAD + kt * 16 + b_c);
                    bl2[2*np][0] = r[0]; bl2[2*np][1] = r[1];
                    bl2[2*np+1][0] = r[2]; bl2[2*np+1][1] = r[3];
                }
                #pragma unroll
                for (int nt = 0; nt < 8; nt++) {
                    mma16816(sacc[nt], qfh[kt], bh2[nt]);
                    mma16816(sacc[nt], qfh[kt], bl2[nt]);
                    mma16816(sacc[nt], qfl[kt], bh2[nt]);
                }
            }

            if (jt * 64 + 63 > qrow0) {
                #pragma unroll
                for (int nt = 0; nt < 8; nt++) {
                    int key0 = jt * 64 + nt * 8 + t2;
                    if (key0     > qrow0)     sacc[nt][0] = -1e30f;
                    if (key0 + 1 > qrow0)     sacc[nt][1] = -1e30f;
                    if (key0     > qrow0 + 8) sacc[nt][2] = -1e30f;
                    if (key0 + 1 > qrow0 + 8) sacc[nt][3] = -1e30f;
                }
            }

            float mx0 = -1e30f, mx1 = -1e30f;
            #pragma unroll
            for (int nt = 0; nt < 8; nt++) {
                mx0 = fmaxf(mx0, fmaxf(sacc[nt][0], sacc[nt][1]));
                mx1 = fmaxf(mx1, fmaxf(sacc[nt][2], sacc[nt][3]));
            }
            mx0 = fmaxf(mx0, __shfl_xor_sync(0xffffffffu, mx0, 1));
            mx0 = fmaxf(mx0, __shfl_xor_sync(0xffffffffu, mx0, 2));
            mx1 = fmaxf(mx1, __shfl_xor_sync(0xffffffffu, mx1, 1));
            mx1 = fmaxf(mx1, __shfl_xor_sync(0xffffffffu, mx1, 2));
            float mn0 = fmaxf(m0, mx0), mn1 = fmaxf(m1, mx1);
            float a0 = __expf(m0 - mn0), a1 = __expf(m1 - mn1);
            m0 = mn0; m1 = mn1;
            float rs0 = 0.f, rs1 = 0.f;
            #pragma unroll
            for (int nt = 0; nt < 8; nt++) {
                sacc[nt][0] = __expf(sacc[nt][0] - mn0); rs0 += sacc[nt][0];
                sacc[nt][1] = __expf(sacc[nt][1] - mn0); rs0 += sacc[nt][1];
                sacc[nt][2] = __expf(sacc[nt][2] - mn1); rs1 += sacc[nt][2];
                sacc[nt][3] = __expf(sacc[nt][3] - mn1); rs1 += sacc[nt][3];
            }
            rs0 += __shfl_xor_sync(0xffffffffu, rs0, 1);
            rs0 += __shfl_xor_sync(0xffffffffu, rs0, 2);
            rs1 += __shfl_xor_sync(0xffffffffu, rs1, 1);
            rs1 += __shfl_xor_sync(0xffffffffu, rs1, 2);
            l0 = l0 * a0 + rs0;
            l1 = l1 * a1 + rs1;
            #pragma unroll
            for (int nt = 0; nt < 8; nt++) {
                oacc[nt][0] *= a0; oacc[nt][1] *= a0;
                oacc[nt][2] *= a1; oacc[nt][3] *= a1;
            }

            #pragma unroll
            for (int j = 0; j < 4; j++) {
                uint32_t ph[4], pl4[4];
                ph[0] = pack2(sacc[2*j][0],   sacc[2*j][1],   pl4[0]);
                ph[1] = pack2(sacc[2*j][2],   sacc[2*j][3],   pl4[1]);
                ph[2] = pack2(sacc[2*j+1][0], sacc[2*j+1][1], pl4[2]);
                ph[3] = pack2(sacc[2*j+1][2], sacc[2*j+1][3], pl4[3]);
                #pragma unroll
                for (int nt = 0; nt < 8; nt++) {
                    uint32_t vhf[2], vlf[2];
                    ldmx2t(vhf[0], vhf[1], VHs + (j * 16 + (lane & 15)) * FPAD + nt * 8);
                    ldmx2t(vlf[0], vlf[1], VLs + (j * 16 + (lane & 15)) * FPAD + nt * 8);
                    mma16816(oacc[nt], ph, vhf);
                    mma16816(oacc[nt], ph, vlf);
                    mma16816(oacc[nt], pl4, vhf);
                }
            }
        }
    }

    float inv0 = 1.f / l0, inv1 = 1.f / l1;
    long row0 = (long)b * Tq + qi * 128 + warp * 16 + g;
    #pragma unroll
    for (int nt = 0; nt < 8; nt++) {
        int col = h * HDq + nt * 8 + t2;
        #pragma unroll
        for (int half = 0; half < 2; half++) {
            long r = row0 + half * 8;
            float v0 = oacc[nt][half * 2 + 0] * (half ? inv1 : inv0);
            float v1 = oacc[nt][half * 2 + 1] * (half ? inv1 : inv0);
            __nv_bfloat16 h0 = __float2bfloat16(v0);
            __nv_bfloat16 h1 = __float2bfloat16(v1);
            __nv_bfloat162 hw(h0, h1);
            *(uint32_t*)(out_hi + r * Dq + col) = *(uint32_t*)&hw;
            uint16_t l8 = (uint16_t)to_e4m3((v0 - __bfloat162float(h0)) * LOSCALE)
                        | ((uint16_t)to_e4m3((v1 - __bfloat162float(h1)) * LOSCALE) << 8);
            uint16_t h8 = (uint16_t)to_e4m3(__bfloat162float(h0))
                        | ((uint16_t)to_e4m3(__bfloat162float(h1)) << 8);
            *(uint16_t*)(out8 + r * 2 * Dq + col)      = l8;
            *(uint16_t*)(out8 + r * 2 * Dq + Dq + col) = h8;
        }
    }
}

// ---------------------------------------------------------------------------
// Launch
// ---------------------------------------------------------------------------
extern "C" void kernel_launch(void* const* d_in, const int* in_sizes, int n_in,
                              void* d_out, int out_size)
{
    const float* x   = (const float*)d_in[0];
    const float* Wq  = (const float*)d_in[1];
    const float* Wk  = (const float*)d_in[2];
    const float* Wv  = (const float*)d_in[3];
    const float* Wp  = (const float*)d_in[4];
    const float* bp  = (const float*)d_in[5];
    const float* W1  = (const float*)d_in[6];
    const float* b1  = (const float*)d_in[7];
    const float* W2  = (const float*)d_in[8];
    const float* b2  = (const float*)d_in[9];
    const float* g1  = (const float*)d_in[10];
    const float* be1 = (const float*)d_in[11];
    const float* g2  = (const float*)d_in[12];
    const float* be2 = (const float*)d_in[13];
    float* out = (float*)d_out;

    __nv_bfloat16 *p_h_hi, *p_wqkv_hi, *p_wp_hi, *p_w1_hi, *p_w2_hi;
    __nv_bfloat16 *p_attn_hi, *p_ff_hi, *p_qkvh, *p_qkvl;
    uint8_t *p_h8, *p_wqkv8, *p_wp8, *p_w18, *p_w28, *p_attn8, *p_ff8;
    float *p_x1;
    cudaGetSymbolAddress((void**)&p_h_hi,    g_h_hi);
    cudaGetSymbolAddress((void**)&p_h8,      g_h8);
    cudaGetSymbolAddress((void**)&p_wqkv_hi, g_wqkv_hi);
    cudaGetSymbolAddress((void**)&p_wqkv8,   g_wqkv8);
    cudaGetSymbolAddress((void**)&p_wp_hi,   g_wp_hi);
    cudaGetSymbolAddress((void**)&p_wp8,     g_wp8);
    cudaGetSymbolAddress((void**)&p_w1_hi,   g_w1_hi);
    cudaGetSymbolAddress((void**)&p_w18,     g_w18);
    cudaGetSymbolAddress((void**)&p_w2_hi,   g_w2_hi);
    cudaGetSymbolAddress((void**)&p_w28,     g_w28);
    cudaGetSymbolAddress((void**)&p_qkvh,    g_qkvh);
    cudaGetSymbolAddress((void**)&p_qkvl,    g_qkvl);
    cudaGetSymbolAddress((void**)&p_attn_hi, g_attn_hi);
    cudaGetSymbolAddress((void**)&p_attn8,   g_attn8);
    cudaGetSymbolAddress((void**)&p_x1,      g_x1);
    cudaGetSymbolAddress((void**)&p_ff_hi,   g_ff_hi);
    cudaGetSymbolAddress((void**)&p_ff8,     g_ff8);

    cudaFuncSetAttribute(gemm_hi8<2>, cudaFuncAttributeMaxDynamicSharedMemorySize, GEMM_SMEM);
    cudaFuncSetAttribute(gemm_hi8<3>, cudaFuncAttributeMaxDynamicSharedMemorySize, GEMM_SMEM);
    cudaFuncSetAttribute(gemm_hi8<4>, cudaFuncAttributeMaxDynamicSharedMemorySize, GEMM_SMEM);
    cudaFuncSetAttribute(flash_tc,    cudaFuncAttributeMaxDynamicSharedMemorySize, FLASH_SMEM);

    // weight prep
    prep_wqkv_tiled<<<dim3(HDq / 32, Dq / 32, 48), dim3(32, 8)>>>(Wq, Wk, Wv, p_wqkv_hi, p_wqkv8);
    transpose_split8<<<dim3(Dq / 32, Dq / 32),  dim3(32, 8)>>>(Wp, p_wp_hi, p_wp8, Dq, Dq);
    transpose_split8<<<dim3(DFF / 32, Dq / 32), dim3(32, 8)>>>(W1, p_w1_hi, p_w18, Dq, DFF);
    transpose_split8<<<dim3(Dq / 32, DFF / 32), dim3(32, 8)>>>(W2, p_w2_hi, p_w28, DFF, Dq);

    // LN1
    ln_split8<<<Mq, 256>>>(x, g1, be1, p_h_hi, p_h8);
    // QKV projection -> split bf16 (hi/lo) for flash, q prescaled
    gemm_hi8<4><<<dim3(3 * Dq / 256, Mq / 128), 256, GEMM_SMEM>>>(
        p_h_hi, p_h8, p_wqkv_hi, p_wqkv8, nullptr, nullptr,
        nullptr, p_qkvh, p_qkvl, nullptr, 3 * Dq, Dq);
    // flash attention -> hi bf16 + fp8 concat
    flash_tc<<<dim3(Tq / 128, Bq * Hq), 256, FLASH_SMEM>>>(
        p_qkvh, p_qkvl, p_attn_hi, p_attn8);
    // output projection + bias + residual(x)
    gemm_hi8<2><<<dim3(Dq / 256, Mq / 128), 256, GEMM_SMEM>>>(
        p_attn_hi, p_attn8, p_wp_hi, p_wp8, bp, x,
        p_x1, nullptr, nullptr, nullptr, Dq, Dq);
    // LN2
    ln_split8<<<Mq, 256>>>(p_x1, g2, be2, p_h_hi, p_h8);
    // FFN up + bias + relu -> hi bf16 + fp8 concat
    gemm_hi8<3><<<dim3(DFF / 256, Mq / 128), 256, GEMM_SMEM>>>(
        p_h_hi, p_h8, p_w1_hi, p_w18, b1, nullptr,
        nullptr, p_ff_hi, nullptr, p_ff8, DFF, Dq);
    // FFN down + bias + residual(x1) -> d_out
    gemm_hi8<2><<<dim3(Dq / 256, Mq / 128), 256, GEMM_SMEM>>>(
        p_ff_hi, p_ff8, p_w2_hi, p_w28, b2, p_x1,
        out, nullptr, nullptr, nullptr, Dq, DFF);
}

// round 8
// speedup vs baseline: 1.5528x; 1.5528x over previous
#include <cuda_runtime.h>
#include <cuda_bf16.h>
#include <cuda_fp16.h>
#include <stdint.h>

// Problem constants
#define Bq   4
#define Tq   2048
#define Dq   1024
#define Hq   16
#define HDq  64
#define Mq   (Bq * Tq)        // 8192
#define DFF  (4 * Dq)         // 4096
#define LN_EPS 1e-5f
#define ATT_SCALE 0.125f

// ---------------------------------------------------------------------------
// Scratch
// ---------------------------------------------------------------------------
__device__ __half        g_h[Mq * Dq];                                // LN out fp16
__device__ __half        g_wqkv_hi[3*Dq*Dq], g_wqkv_lo[3*Dq*Dq];      // [3D][D]
__device__ __half        g_wp_hi[Dq*Dq],     g_wp_lo[Dq*Dq];          // [D][D] transposed
__device__ __half        g_w1_hi[DFF*Dq],    g_w1_lo[DFF*Dq];         // [4D][D]
__device__ __half        g_w2_hi[Dq*DFF],    g_w2_lo[Dq*DFF];         // [D][4D]
__device__ __nv_bfloat16 g_qkvh[Mq * 3 * Dq], g_qkvl[Mq * 3 * Dq];    // flash input (q pre-scaled)
__device__ __half        g_attn[Mq * Dq];                             // flash out fp16
__device__ float         g_x1[Mq * Dq];
__device__ __half        g_ff[Mq * DFF];                              // FFN hidden fp16

// ---------------------------------------------------------------------------
// Helpers
// ---------------------------------------------------------------------------
__device__ __forceinline__ void split_f16(float v, __half& hi, __half& lo) {
    hi = __float2half(v);
    lo = __float2half(v - __half2float(hi));
}

__device__ __forceinline__ uint32_t pack2(float x, float y, uint32_t& lo) {
    __nv_bfloat16 hx = __float2bfloat16(x), hy = __float2bfloat16(y);
    __nv_bfloat16 lx = __float2bfloat16(x - __bfloat162float(hx));
    __nv_bfloat16 ly = __float2bfloat16(y - __bfloat162float(hy));
    __nv_bfloat162 h2(hx, hy), l2(lx, ly);
    lo = *reinterpret_cast<uint32_t*>(&l2);
    return *reinterpret_cast<uint32_t*>(&h2);
}

__device__ __forceinline__ void mma16816(float* c, const uint32_t* a, const uint32_t* b) {
    asm volatile(
        "mma.sync.aligned.m16n8k16.row.col.f32.bf16.bf16.f32 "
        "{%0,%1,%2,%3}, {%4,%5,%6,%7}, {%8,%9}, {%0,%1,%2,%3};"
        : "+f"(c[0]), "+f"(c[1]), "+f"(c[2]), "+f"(c[3])
        : "r"(a[0]), "r"(a[1]), "r"(a[2]), "r"(a[3]), "r"(b[0]), "r"(b[1]));
}

__device__ __forceinline__ void mma_f16(float* c, const uint32_t* a, const uint32_t* b) {
    asm volatile(
        "mma.sync.aligned.m16n8k16.row.col.f32.f16.f16.f32 "
        "{%0,%1,%2,%3}, {%4,%5,%6,%7}, {%8,%9}, {%0,%1,%2,%3};"
        : "+f"(c[0]), "+f"(c[1]), "+f"(c[2]), "+f"(c[3])
        : "r"(a[0]), "r"(a[1]), "r"(a[2]), "r"(a[3]), "r"(b[0]), "r"(b[1]));
}

__device__ __forceinline__ void ldmx4(uint32_t* r, const void* p) {
    uint32_t a = (uint32_t)__cvta_generic_to_shared(p);
    asm volatile("ldmatrix.sync.aligned.m8n8.x4.shared.b16 {%0,%1,%2,%3}, [%4];"
                 : "=r"(r[0]), "=r"(r[1]), "=r"(r[2]), "=r"(r[3]) : "r"(a));
}

__device__ __forceinline__ void ldmx2t(uint32_t& r0, uint32_t& r1, const void* p) {
    uint32_t a = (uint32_t)__cvta_generic_to_shared(p);
    asm volatile("ldmatrix.sync.aligned.m8n8.x2.trans.shared.b16 {%0,%1}, [%2];"
                 : "=r"(r0), "=r"(r1) : "r"(a));
}

__device__ __forceinline__ void cp16(void* sdst, const void* gsrc) {
    unsigned sa = (unsigned)__cvta_generic_to_shared(sdst);
    asm volatile("cp.async.cg.shared.global [%0], [%1], 16;" :: "r"(sa), "l"(gsrc));
}
#define CP_COMMIT() asm volatile("cp.async.commit_group;")
#define CP_WAIT0()  asm volatile("cp.async.wait_group 0;")
#define CP_WAIT1()  asm volatile("cp.async.wait_group 1;")

// ---------------------------------------------------------------------------
// Weight prep: tiled transpose + fp16 hi/lo split
// ---------------------------------------------------------------------------
__global__ void prep_wqkv_tiled(const float* __restrict__ Wq,
                                const float* __restrict__ Wk,
                                const float* __restrict__ Wv,
                                __half* __restrict__ o_hi,
                                __half* __restrict__ o_lo)
{
    __shared__ float t[32][33];
    int s = blockIdx.z >> 4, h = blockIdx.z & 15;
    const float* W = (s == 0) ? Wq : (s == 1) ? Wk : Wv;
    const float* in = W + (long)h * Dq * HDq;
    int d0 = blockIdx.y * 32, hd0 = blockIdx.x * 32;
    int tx = threadIdx.x, ty = threadIdx.y;
    #pragma unroll
    for (int i = 0; i < 32; i += 8)
        t[ty + i][tx] = in[(long)(d0 + ty + i) * HDq + hd0 + tx];
    __syncthreads();
    long nrow = (long)s * Dq + h * HDq + hd0;
    #pragma unroll
    for (int i = 0; i < 32; i += 8) {
        float v = t[tx][ty + i];
        long o = (nrow + ty + i) * Dq + d0 + tx;
        split_f16(v, o_hi[o], o_lo[o]);
    }
}

// in: [K][N] fp32 -> out: [N][K] fp16 hi/lo
__global__ void transpose_split_t(const float* __restrict__ in,
                                  __half* __restrict__ o_hi,
                                  __half* __restrict__ o_lo,
                                  int K, int N)
{
    __shared__ float t[32][33];
    int k0 = blockIdx.y * 32, n0 = blockIdx.x * 32;
    int tx = threadIdx.x, ty = threadIdx.y;
    #pragma unroll
    for (int i = 0; i < 32; i += 8)
        t[ty + i][tx] = in[(long)(k0 + ty + i) * N + n0 + tx];
    __syncthreads();
    #pragma unroll
    for (int i = 0; i < 32; i += 8) {
        float v = t[tx][ty + i];
        long o = (long)(n0 + ty + i) * K + k0 + tx;
        split_f16(v, o_hi[o], o_lo[o]);
    }
}

// ---------------------------------------------------------------------------
// LayerNorm -> fp16
// ---------------------------------------------------------------------------
__global__ void ln_f16(const float* __restrict__ x,
                       const float* __restrict__ g,
                       const float* __restrict__ b,
                       __half* __restrict__ o)
{
    __shared__ float red[16];
    int row = blockIdx.x;
    int t = threadIdx.x;
    const float4* xr = (const float4*)(x + (long)row * Dq);
    float4 v = xr[t];
    float s  = v.x + v.y + v.z + v.w;
    float ss = v.x * v.x + v.y * v.y + v.z * v.z + v.w * v.w;
    #pragma unroll
    for (int o2 = 16; o2 >= 1; o2 >>= 1) {
        s  += __shfl_xor_sync(0xffffffffu, s,  o2);
        ss += __shfl_xor_sync(0xffffffffu, ss, o2);
    }
    if ((t & 31) == 0) { red[t >> 5] = s; red[8 + (t >> 5)] = ss; }
    __syncthreads();
    float stot = 0.f, sstot = 0.f;
    #pragma unroll
    for (int w = 0; w < 8; w++) { stot += red[w]; sstot += red[8 + w]; }
    float mu  = stot * (1.f / Dq);
    float var = sstot * (1.f / Dq) - mu * mu;
    float inv = rsqrtf(var + LN_EPS);
    float4 gg = ((const float4*)g)[t];
    float4 bb = ((const float4*)b)[t];
    __half2 p0 = __floats2half2_rn((v.x - mu) * inv * gg.x + bb.x,
                                   (v.y - mu) * inv * gg.y + bb.y);
    __half2 p1 = __floats2half2_rn((v.z - mu) * inv * gg.z + bb.z,
                                   (v.w - mu) * inv * gg.w + bb.w);
    long base = (long)row * Dq + t * 4;
    *(__half2*)(o + base)     = p0;
    *(__half2*)(o + base + 2) = p1;
}

// ---------------------------------------------------------------------------
// fp16 two-term GEMM: C = A @ (Bhi + Blo).  A fp16 [M][K] (single),
// B pre-transposed fp16 hi/lo [N][K].  Tile 128x256, 8 warps (2x4),
// warp 64x64, 3-stage cp.async, ldmatrix.x4 fragments, 1 barrier/K-step.
// EPI: 2 +bias+residual fp32; 3 +bias+relu -> fp16; 4 -> bf16 hi/lo w/ q prescale
// ---------------------------------------------------------------------------
#define KPAD 40
#define AST (128 * KPAD)
#define BST (256 * KPAD)
#define STAGE_U (AST + 2 * BST)            // 25600 halfwords = 51200 B
#define GEMM_SMEM (3 * STAGE_U * 2)        // 153600 B

template <int EPI>
__global__ void __launch_bounds__(256, 1)
gemm_f16x2(const __half* __restrict__ A,
           const __half* __restrict__ Bhi,
           const __half* __restrict__ Blo,
           const float* __restrict__ bias,
           const float* __restrict__ res,
           float* __restrict__ C,
           __nv_bfloat16* __restrict__ Chi,
           __nv_bfloat16* __restrict__ Clo,
           __half* __restrict__ Ch,
           int N, int K)
{
    extern __shared__ __half smem[];
    const int tid  = threadIdx.x;
    const int lane = tid & 31;
    const int warp = tid >> 5;
    const int wm = warp >> 2;
    const int wn = warp & 3;
    const int a_r = lane & 15;
    const int a_c = (lane >> 4) << 3;
    const int b_r = (lane & 7) + ((lane >> 4) << 3);
    const int b_c = ((lane >> 3) & 1) << 3;

    const int bm = blockIdx.y, bn = blockIdx.x;
    const __half* A_b   = A   + (long)bm * 128 * K;
    const __half* Bhi_b = Bhi + (long)bn * 256 * K;
    const __half* Blo_b = Blo + (long)bn * 256 * K;

    auto sA  = [&](int st) -> __half* { return smem + st * STAGE_U; };
    auto sBh = [&](int st) -> __half* { return smem + st * STAGE_U + AST; };
    auto sBl = [&](int st) -> __half* { return smem + st * STAGE_U + AST + BST; };

    auto ld_stage = [&](int st, int kt) {
        long k0 = (long)kt * 32;
        #pragma unroll
        for (int i = 0; i < 2; i++) {                   // A: 512 chunks
            int c = tid + i * 256;
            int row = c >> 2, ch = (c & 3) * 8;
            cp16(sA(st) + row * KPAD + ch, A_b + (long)row * K + k0 + ch);
        }
        #pragma unroll
        for (int i = 0; i < 4; i++) {                   // Bhi/Blo: 1024 chunks each
            int c = tid + i * 256;
            int row = c >> 2, ch = (c & 3) * 8;
            long go = (long)row * K + k0 + ch;
            int  so = row * KPAD + ch;
            cp16(sBh(st) + so, Bhi_b + go);
            cp16(sBl(st) + so, Blo_b + go);
        }
    };

    float acc[4][8][4];
    #pragma unroll
    for (int i = 0; i < 4; i++)
        #pragma unroll
        for (int j = 0; j < 8; j++)
            #pragma unroll
            for (int r = 0; r < 4; r++) acc[i][j][r] = 0.f;

    const int KT = K / 32;
    ld_stage(0, 0); CP_COMMIT();
    ld_stage(1, 1); CP_COMMIT();

    int st = 0;
    for (int kt = 0; kt < KT; kt++) {
        if (kt + 1 < KT) { CP_WAIT1(); } else { CP_WAIT0(); }
        __syncthreads();
        if (kt + 2 < KT) {
            int wst = st + 2; if (wst >= 3) wst -= 3;
            ld_stage(wst, kt + 2);
            CP_COMMIT();
        }

        const __half* pA  = sA(st);
        const __half* pBh = sBh(st);
        const __half* pBl = sBl(st);

        #pragma unroll
        for (int ks = 0; ks < 2; ks++) {
            const int k16 = ks * 16;
            uint32_t af[4][4], bh[8][2], bl[8][2];
            #pragma unroll
            for (int mt = 0; mt < 4; mt++)
                ldmx4(af[mt], pA + (wm * 64 + mt * 16 + a_r) * KPAD + k16 + a_c);
            #pragma unroll
            for (int np = 0; np < 4; np++) {
                int row = wn * 64 + np * 16 + b_r;
                uint32_t r[4];
                ldmx4(r, pBh + row * KPAD + k16 + b_c);
                bh[2*np][0] = r[0]; bh[2*np][1] = r[1];
                bh[2*np+1][0] = r[2]; bh[2*np+1][1] = r[3];
                ldmx4(r, pBl + row * KPAD + k16 + b_c);
                bl[2*np][0] = r[0]; bl[2*np][1] = r[1];
                bl[2*np+1][0] = r[2]; bl[2*np+1][1] = r[3];
            }
            #pragma unroll
            for (int mt = 0; mt < 4; mt++)
                #pragma unroll
                for (int nt = 0; nt < 8; nt++) {
                    mma_f16(acc[mt][nt], af[mt], bh[nt]);
                    mma_f16(acc[mt][nt], af[mt], bl[nt]);
                }
        }
        if (++st == 3) st = 0;
    }

    // epilogue
    const int lr4 = lane >> 2;
    const int lc2 = (lane & 3) * 2;
    #pragma unroll
    for (int mt = 0; mt < 4; mt++) {
        #pragma unroll
        for (int nt = 0; nt < 8; nt++) {
            int c = bn * 256 + wn * 64 + nt * 8 + lc2;
            #pragma unroll
            for (int half = 0; half < 2; half++) {
                int r = bm * 128 + wm * 64 + mt * 16 + lr4 + half * 8;
                float v0 = acc[mt][nt][half * 2 + 0];
                float v1 = acc[mt][nt][half * 2 + 1];
                long off = (long)r * N + c;
                if (EPI == 2) {
                    float2 bv = *(const float2*)(bias + c);
                    float2 rv = *(const float2*)(res + off);
                    *(float2*)(C + off) = make_float2(v0 + bv.x + rv.x,
                                                      v1 + bv.y + rv.y);
                } else if (EPI == 3) {
                    float2 bv = *(const float2*)(bias + c);
                    v0 = fmaxf(v0 + bv.x, 0.f);
                    v1 = fmaxf(v1 + bv.y, 0.f);
                    *(__half2*)(Ch + off) = __floats2half2_rn(v0, v1);
                } else {  // EPI == 4: bf16 hi/lo for flash, q cols prescaled
                    float scale = (c < Dq) ? ATT_SCALE : 1.f;
                    uint32_t lo;
                    uint32_t hi = pack2(v0 * scale, v1 * scale, lo);
                    *(uint32_t*)(Chi + off) = hi;
                    *(uint32_t*)(Clo + off) = lo;
                }
            }
        }
    }
}

// ---------------------------------------------------------------------------
// Tensor-core flash attention (bf16x3, proven R6 version); epilogue -> fp16
// ---------------------------------------------------------------------------
#define FPAD 72
#define FLASH_SMEM ((2 * 128 * FPAD + 2 * 4 * 64 * FPAD) * 2)

__global__ void __launch_bounds__(256)
flash_tc(const __nv_bfloat16* __restrict__ qkvh,
         const __nv_bfloat16* __restrict__ qkvl,
         __half* __restrict__ outp)
{
    extern __shared__ __nv_bfloat16 sm[];
    __nv_bfloat16* QH = sm;
    __nv_bfloat16* QL = sm + 128 * FPAD;

    const int qi  = gridDim.x - 1 - blockIdx.x;
    const int bh  = blockIdx.y;
    const int b   = bh >> 4;
    const int h   = bh & 15;
    const int tid  = threadIdx.x;
    const int lane = tid & 31;
    const int warp = tid >> 5;
    const int g  = lane >> 2;
    const int t2 = (lane & 3) * 2;
    const int a_r = lane & 15;
    const int a_c = (lane >> 4) << 3;
    const int b_r = (lane & 7) + ((lane >> 4) << 3);
    const int b_c = ((lane >> 3) & 1) << 3;

    const long rb = (long)b * Tq;
    const __nv_bfloat16* qh = qkvh + (rb + qi * 128) * (3 * Dq) + h * HDq;
    const __nv_bfloat16* ql = qkvl + (rb + qi * 128) * (3 * Dq) + h * HDq;
    const __nv_bfloat16* kh = qkvh + rb * (3 * Dq) + Dq + h * HDq;
    const __nv_bfloat16* kl = qkvl + rb * (3 * Dq) + Dq + h * HDq;
    const __nv_bfloat16* vh = qkvh + rb * (3 * Dq) + 2 * Dq + h * HDq;
    const __nv_bfloat16* vl = qkvl + rb * (3 * Dq) + 2 * Dq + h * HDq;

    auto kvbase = [&](int st) -> __nv_bfloat16* {
        return sm + 2 * 128 * FPAD + st * (4 * 64 * FPAD);
    };
    auto ldkv = [&](int st, int jt) {
        __nv_bfloat16* KB = kvbase(st);
        #pragma unroll
        for (int i = 0; i < 2; i++) {
            int c = tid + i * 256;
            int row = c >> 3;
            int c8 = (c & 7) * 8;
            long go = (long)(jt * 64 + row) * (3 * Dq) + c8;
            int so = row * FPAD + c8;
            cp16(KB + so,                 kh + go);
            cp16(KB + 64 * FPAD + so,     kl + go);
            cp16(KB + 2 * 64 * FPAD + so, vh + go);
            cp16(KB + 3 * 64 * FPAD + so, vl + go);
        }
    };

    #pragma unroll
    for (int i = 0; i < 4; i++) {
        int c = tid + i * 256;
        int row = c >> 3;
        int c8 = (c & 7) * 8;
        cp16(QH + row * FPAD + c8, qh + (long)row * (3 * Dq) + c8);
        cp16(QL + row * FPAD + c8, ql + (long)row * (3 * Dq) + c8);
    }
    ldkv(0, 0);
    CP_COMMIT();

    float oacc[8][4];
    #pragma unroll
    for (int nt = 0; nt < 8; nt++)
        #pragma unroll
        for (int e = 0; e < 4; e++) oacc[nt][e] = 0.f;
    float m0 = -1e30f, m1 = -1e30f, l0 = 0.f, l1 = 0.f;

    uint32_t qfh[4][4], qfl[4][4];
    const int qrow0 = qi * 128 + warp * 16 + g;
    const int jmax = 2 * qi + 1;

    for (int jt = 0; jt <= jmax; jt++) {
        CP_WAIT0();
        __syncthreads();
        if (jt < jmax) { ldkv((jt + 1) & 1, jt + 1); CP_COMMIT(); }

        if (jt == 0) {
            #pragma unroll
            for (int kt = 0; kt < 4; kt++) {
                int row = warp * 16 + a_r;
                ldmx4(qfh[kt], QH + row * FPAD + kt * 16 + a_c);
                ldmx4(qfl[kt], QL + row * FPAD + kt * 16 + a_c);
            }
        }

        if (jt * 64 <= qi * 128 + warp * 16 + 15) {
            __nv_bfloat16* KB = kvbase(jt & 1);
            const __nv_bfloat16* KHs = KB;
            const __nv_bfloat16* KLs = KB + 64 * FPAD;
            const __nv_bfloat16* VHs = KB + 2 * 64 * FPAD;
            const __nv_bfloat16* VLs = KB + 3 * 64 * FPAD;

            float sacc[8][4];
            #pragma unroll
            for (int nt = 0; nt < 8; nt++)
                #pragma unroll
                for (int e = 0; e < 4; e++) sacc[nt][e] = 0.f;

            #pragma unroll
            for (int kt = 0; kt < 4; kt++) {
                uint32_t bh2[8][2], bl2[8][2];
                #pragma unroll
                for (int np = 0; np < 4; np++) {
                    int row = np * 16 + b_r;
                    uint32_t r[4];
                    ldmx4(r, KHs + row * FPAD + kt * 16 + b_c);
                    bh2[2*np][0] = r[0]; bh2[2*np][1] = r[1];
                    bh2[2*np+1][0] = r[2]; bh2[2*np+1][1] = r[3];
                    ldmx4(r, KLs + row * FPAD + kt * 16 + b_c);
                    bl2[2*np][0] = r[0]; bl2[2*np][1] = r[1];
                    bl2[2*np+1][0] = r[2]; bl2[2*np+1][1] = r[3];
                }
                #pragma unroll
                for (int nt = 0; nt < 8; nt++) {
                    mma16816(sacc[nt], qfh[kt], bh2[nt]);
                    mma16816(sacc[nt], qfh[kt], bl2[nt]);
                    mma16816(sacc[nt], qfl[kt], bh2[nt]);
                }
            }

            if (jt * 64 + 63 > qrow0) {
                #pragma unroll
                for (int nt = 0; nt < 8; nt++) {
                    int key0 = jt * 64 + nt * 8 + t2;
                    if (key0     > qrow0)     sacc[nt][0] = -1e30f;
                    if (key0 + 1 > qrow0)     sacc[nt][1] = -1e30f;
                    if (key0     > qrow0 + 8) sacc[nt][2] = -1e30f;
                    if (key0 + 1 > qrow0 + 8) sacc[nt][3] = -1e30f;
                }
            }

            float mx0 = -1e30f, mx1 = -1e30f;
            #pragma unroll
            for (int nt = 0; nt < 8; nt++) {
                mx0 = fmaxf(mx0, fmaxf(sacc[nt][0], sacc[nt][1]));
                mx1 = fmaxf(mx1, fmaxf(sacc[nt][2], sacc[nt][3]));
            }
            mx0 = fmaxf(mx0, __shfl_xor_sync(0xffffffffu, mx0, 1));
            mx0 = fmaxf(mx0, __shfl_xor_sync(0xffffffffu, mx0, 2));
            mx1 = fmaxf(mx1, __shfl_xor_sync(0xffffffffu, mx1, 1));
            mx1 = fmaxf(mx1, __shfl_xor_sync(0xffffffffu, mx1, 2));
            float mn0 = fmaxf(m0, mx0), mn1 = fmaxf(m1, mx1);
            float a0 = __expf(m0 - mn0), a1 = __expf(m1 - mn1);
            m0 = mn0; m1 = mn1;
            float rs0 = 0.f, rs1 = 0.f;
            #pragma unroll
            for (int nt = 0; nt < 8; nt++) {
                sacc[nt][0] = __expf(sacc[nt][0] - mn0); rs0 += sacc[nt][0];
                sacc[nt][1] = __expf(sacc[nt][1] - mn0); rs0 += sacc[nt][1];
                sacc[nt][2] = __expf(sacc[nt][2] - mn1); rs1 += sacc[nt][2];
                sacc[nt][3] = __expf(sacc[nt][3] - mn1); rs1 += sacc[nt][3];
            }
            rs0 += __shfl_xor_sync(0xffffffffu, rs0, 1);
            rs0 += __shfl_xor_sync(0xffffffffu, rs0, 2);
            rs1 += __shfl_xor_sync(0xffffffffu, rs1, 1);
            rs1 += __shfl_xor_sync(0xffffffffu, rs1, 2);
            l0 = l0 * a0 + rs0;
            l1 = l1 * a1 + rs1;
            #pragma unroll
            for (int nt = 0; nt < 8; nt++) {
                oacc[nt][0] *= a0; oacc[nt][1] *= a0;
                oacc[nt][2] *= a1; oacc[nt][3] *= a1;
            }

            #pragma unroll
            for (int j = 0; j < 4; j++) {
                uint32_t ph[4], pl4[4];
                ph[0] = pack2(sacc[2*j][0],   sacc[2*j][1],   pl4[0]);
                ph[1] = pack2(sacc[2*j][2],   sacc[2*j][3],   pl4[1]);
                ph[2] = pack2(sacc[2*j+1][0], sacc[2*j+1][1], pl4[2]);
                ph[3] = pack2(sacc[2*j+1][2], sacc[2*j+1][3], pl4[3]);
                #pragma unroll
                for (int nt = 0; nt < 8; nt++) {
                    uint32_t vhf[2], vlf[2];
                    ldmx2t(vhf[0], vhf[1], VHs + (j * 16 + (lane & 15)) * FPAD + nt * 8);
                    ldmx2t(vlf[0], vlf[1], VLs + (j * 16 + (lane & 15)) * FPAD + nt * 8);
                    mma16816(oacc[nt], ph, vhf);
                    mma16816(oacc[nt], ph, vlf);
                    mma16816(oacc[nt], pl4, vhf);
                }
            }
        }
    }

    float inv0 = 1.f / l0, inv1 = 1.f / l1;
    long row0 = (long)b * Tq + qi * 128 + warp * 16 + g;
    #pragma unroll
    for (int nt = 0; nt < 8; nt++) {
        int col = h * HDq + nt * 8 + t2;
        *(__half2*)(outp + row0 * Dq + col) =
            __floats2half2_rn(oacc[nt][0] * inv0, oacc[nt][1] * inv0);
        *(__half2*)(outp + (row0 + 8) * Dq + col) =
            __floats2half2_rn(oacc[nt][2] * inv1, oacc[nt][3] * inv1);
    }
}

// ---------------------------------------------------------------------------
// Launch
// ---------------------------------------------------------------------------
extern "C" void kernel_launch(void* const* d_in, const int* in_sizes, int n_in,
                              void* d_out, int out_size)
{
    const float* x   = (const float*)d_in[0];
    const float* Wq  = (const float*)d_in[1];
    const float* Wk  = (const float*)d_in[2];
    const float* Wv  = (const float*)d_in[3];
    const float* Wp  = (const float*)d_in[4];
    const float* bp  = (const float*)d_in[5];
    const float* W1  = (const float*)d_in[6];
    const float* b1  = (const float*)d_in[7];
    const float* W2  = (const float*)d_in[8];
    const float* b2  = (const float*)d_in[9];
    const float* g1  = (const float*)d_in[10];
    const float* be1 = (const float*)d_in[11];
    const float* g2  = (const float*)d_in[12];
    const float* be2 = (const float*)d_in[13];
    float* out = (float*)d_out;

    __half *p_h, *p_wqkv_hi, *p_wqkv_lo, *p_wp_hi, *p_wp_lo;
    __half *p_w1_hi, *p_w1_lo, *p_w2_hi, *p_w2_lo, *p_attn, *p_ff;
    __nv_bfloat16 *p_qkvh, *p_qkvl;
    float *p_x1;
    cudaGetSymbolAddress((void**)&p_h,       g_h);
    cudaGetSymbolAddress((void**)&p_wqkv_hi, g_wqkv_hi);
    cudaGetSymbolAddress((void**)&p_wqkv_lo, g_wqkv_lo);
    cudaGetSymbolAddress((void**)&p_wp_hi,   g_wp_hi);
    cudaGetSymbolAddress((void**)&p_wp_lo,   g_wp_lo);
    cudaGetSymbolAddress((void**)&p_w1_hi,   g_w1_hi);
    cudaGetSymbolAddress((void**)&p_w1_lo,   g_w1_lo);
    cudaGetSymbolAddress((void**)&p_w2_hi,   g_w2_hi);
    cudaGetSymbolAddress((void**)&p_w2_lo,   g_w2_lo);
    cudaGetSymbolAddress((void**)&p_qkvh,    g_qkvh);
    cudaGetSymbolAddress((void**)&p_qkvl,    g_qkvl);
    cudaGetSymbolAddress((void**)&p_attn,    g_attn);
    cudaGetSymbolAddress((void**)&p_x1,      g_x1);
    cudaGetSymbolAddress((void**)&p_ff,      g_ff);

    cudaFuncSetAttribute(gemm_f16x2<2>, cudaFuncAttributeMaxDynamicSharedMemorySize, GEMM_SMEM);
    cudaFuncSetAttribute(gemm_f16x2<3>, cudaFuncAttributeMaxDynamicSharedMemorySize, GEMM_SMEM);
    cudaFuncSetAttribute(gemm_f16x2<4>, cudaFuncAttributeMaxDynamicSharedMemorySize, GEMM_SMEM);
    cudaFuncSetAttribute(flash_tc,      cudaFuncAttributeMaxDynamicSharedMemorySize, FLASH_SMEM);

    // weight prep (fp16 hi/lo)
    prep_wqkv_tiled<<<dim3(HDq / 32, Dq / 32, 48), dim3(32, 8)>>>(Wq, Wk, Wv, p_wqkv_hi, p_wqkv_lo);
    transpose_split_t<<<dim3(Dq / 32, Dq / 32),  dim3(32, 8)>>>(Wp, p_wp_hi, p_wp_lo, Dq, Dq);
    transpose_split_t<<<dim3(DFF / 32, Dq / 32), dim3(32, 8)>>>(W1, p_w1_hi, p_w1_lo, Dq, DFF);
    transpose_split_t<<<dim3(Dq / 32, DFF / 32), dim3(32, 8)>>>(W2, p_w2_hi, p_w2_lo, DFF, Dq);

    // LN1 -> fp16
    ln_f16<<<Mq, 256>>>(x, g1, be1, p_h);
    // QKV projection -> bf16 hi/lo for flash, q prescaled
    gemm_f16x2<4><<<dim3(3 * Dq / 256, Mq / 128), 256, GEMM_SMEM>>>(
        p_h, p_wqkv_hi, p_wqkv_lo, nullptr, nullptr,
        nullptr, p_qkvh, p_qkvl, nullptr, 3 * Dq, Dq);
    // flash attention -> fp16
    flash_tc<<<dim3(Tq / 128, Bq * Hq), 256, FLASH_SMEM>>>(p_qkvh, p_qkvl, p_attn);
    // output projection + bias + residual(x)
    gemm_f16x2<2><<<dim3(Dq / 256, Mq / 128), 256, GEMM_SMEM>>>(
        p_attn, p_wp_hi, p_wp_lo, bp, x,
        p_x1, nullptr, nullptr, nullptr, Dq, Dq);
    // LN2 -> fp16
    ln_f16<<<Mq, 256>>>(p_x1, g2, be2, p_h);
    // FFN up + bias + relu -> fp16
    gemm_f16x2<3><<<dim3(DFF / 256, Mq / 128), 256, GEMM_SMEM>>>(
        p_h, p_w1_hi, p_w1_lo, b1, nullptr,
        nullptr, nullptr, nullptr, p_ff, DFF, Dq);
    // FFN down + bias + residual(x1) -> d_out
    gemm_f16x2<2><<<dim3(Dq / 256, Mq / 128), 256, GEMM_SMEM>>>(
        p_ff, p_w2_hi, p_w2_lo, b2, p_x1,
        out, nullptr, nullptr, nullptr, Dq, DFF);
}

// round 9
// speedup vs baseline: 2.1261x; 1.3692x over previous
#include <cuda_runtime.h>
#include <cuda_bf16.h>
#include <cuda_fp16.h>
#include <stdint.h>

// Problem constants
#define Bq   4
#define Tq   2048
#define Dq   1024
#define Hq   16
#define HDq  64
#define Mq   (Bq * Tq)        // 8192
#define DFF  (4 * Dq)         // 4096
#define LN_EPS 1e-5f
#define ATT_SCALE 0.125f

// ---------------------------------------------------------------------------
// Scratch
// ---------------------------------------------------------------------------
__device__ __half g_h[Mq * Dq];                                // LN out fp16
__device__ __half g_wqkv_hi[3*Dq*Dq], g_wqkv_lo[3*Dq*Dq];      // [3D][D]
__device__ __half g_wp_hi[Dq*Dq],     g_wp_lo[Dq*Dq];          // [D][D]
__device__ __half g_w1[DFF*Dq];                                // [4D][D] single fp16
__device__ __half g_w2[Dq*DFF];                                // [D][4D] single fp16
__device__ __half g_qkvh[Mq * 3 * Dq], g_qkvl[Mq * 3 * Dq];    // q pre-scaled; q-lo unused
__device__ __half g_attn[Mq * Dq];                             // flash out fp16
__device__ float  g_x1[Mq * Dq];
__device__ __half g_ff[Mq * DFF];                              // FFN hidden fp16

// ---------------------------------------------------------------------------
// Helpers
// ---------------------------------------------------------------------------
__device__ __forceinline__ void split_f16(float v, __half& hi, __half& lo) {
    hi = __float2half(v);
    lo = __float2half(v - __half2float(hi));
}

__device__ __forceinline__ uint32_t packh2(float x, float y) {
    __half2 h = __floats2half2_rn(x, y);
    return *reinterpret_cast<uint32_t*>(&h);
}

__device__ __forceinline__ void mma_f16(float* c, const uint32_t* a, const uint32_t* b) {
    asm volatile(
        "mma.sync.aligned.m16n8k16.row.col.f32.f16.f16.f32 "
        "{%0,%1,%2,%3}, {%4,%5,%6,%7}, {%8,%9}, {%0,%1,%2,%3};"
        : "+f"(c[0]), "+f"(c[1]), "+f"(c[2]), "+f"(c[3])
        : "r"(a[0]), "r"(a[1]), "r"(a[2]), "r"(a[3]), "r"(b[0]), "r"(b[1]));
}

__device__ __forceinline__ void ldmx4(uint32_t* r, const void* p) {
    uint32_t a = (uint32_t)__cvta_generic_to_shared(p);
    asm volatile("ldmatrix.sync.aligned.m8n8.x4.shared.b16 {%0,%1,%2,%3}, [%4];"
                 : "=r"(r[0]), "=r"(r[1]), "=r"(r[2]), "=r"(r[3]) : "r"(a));
}

__device__ __forceinline__ void ldmx2t(uint32_t& r0, uint32_t& r1, const void* p) {
    uint32_t a = (uint32_t)__cvta_generic_to_shared(p);
    asm volatile("ldmatrix.sync.aligned.m8n8.x2.trans.shared.b16 {%0,%1}, [%2];"
                 : "=r"(r0), "=r"(r1) : "r"(a));
}

__device__ __forceinline__ void cp16(void* sdst, const void* gsrc) {
    unsigned sa = (unsigned)__cvta_generic_to_shared(sdst);
    asm volatile("cp.async.cg.shared.global [%0], [%1], 16;" :: "r"(sa), "l"(gsrc));
}
#define CP_COMMIT() asm volatile("cp.async.commit_group;")
#define CP_WAIT0()  asm volatile("cp.async.wait_group 0;")
#define CP_WAIT1()  asm volatile("cp.async.wait_group 1;")

// ---------------------------------------------------------------------------
// Weight prep
// ---------------------------------------------------------------------------
__global__ void prep_wqkv_tiled(const float* __restrict__ Wq,
                                const float* __restrict__ Wk,
                                const float* __restrict__ Wv,
                                __half* __restrict__ o_hi,
                                __half* __restrict__ o_lo)
{
    __shared__ float t[32][33];
    int s = blockIdx.z >> 4, h = blockIdx.z & 15;
    const float* W = (s == 0) ? Wq : (s == 1) ? Wk : Wv;
    const float* in = W + (long)h * Dq * HDq;
    int d0 = blockIdx.y * 32, hd0 = blockIdx.x * 32;
    int tx = threadIdx.x, ty = threadIdx.y;
    #pragma unroll
    for (int i = 0; i < 32; i += 8)
        t[ty + i][tx] = in[(long)(d0 + ty + i) * HDq + hd0 + tx];
    __syncthreads();
    long nrow = (long)s * Dq + h * HDq + hd0;
    #pragma unroll
    for (int i = 0; i < 32; i += 8) {
        float v = t[tx][ty + i];
        long o = (nrow + ty + i) * Dq + d0 + tx;
        split_f16(v, o_hi[o], o_lo[o]);
    }
}

// in: [K][N] fp32 -> out: [N][K] fp16 hi (+ optional lo)
__global__ void transpose_split_t(const float* __restrict__ in,
                                  __half* __restrict__ o_hi,
                                  __half* __restrict__ o_lo,
                                  int K, int N)
{
    __shared__ float t[32][33];
    int k0 = blockIdx.y * 32, n0 = blockIdx.x * 32;
    int tx = threadIdx.x, ty = threadIdx.y;
    #pragma unroll
    for (int i = 0; i < 32; i += 8)
        t[ty + i][tx] = in[(long)(k0 + ty + i) * N + n0 + tx];
    __syncthreads();
    #pragma unroll
    for (int i = 0; i < 32; i += 8) {
        float v = t[tx][ty + i];
        long o = (long)(n0 + ty + i) * K + k0 + tx;
        __half hi = __float2half(v);
        o_hi[o] = hi;
        if (o_lo) o_lo[o] = __float2half(v - __half2float(hi));
    }
}

// ---------------------------------------------------------------------------
// LayerNorm -> fp16
// ---------------------------------------------------------------------------
__global__ void ln_f16(const float* __restrict__ x,
                       const float* __restrict__ g,
                       const float* __restrict__ b,
                       __half* __restrict__ o)
{
    __shared__ float red[16];
    int row = blockIdx.x;
    int t = threadIdx.x;
    const float4* xr = (const float4*)(x + (long)row * Dq);
    float4 v = xr[t];
    float s  = v.x + v.y + v.z + v.w;
    float ss = v.x * v.x + v.y * v.y + v.z * v.z + v.w * v.w;
    #pragma unroll
    for (int o2 = 16; o2 >= 1; o2 >>= 1) {
        s  += __shfl_xor_sync(0xffffffffu, s,  o2);
        ss += __shfl_xor_sync(0xffffffffu, ss, o2);
    }
    if ((t & 31) == 0) { red[t >> 5] = s; red[8 + (t >> 5)] = ss; }
    __syncthreads();
    float stot = 0.f, sstot = 0.f;
    #pragma unroll
    for (int w = 0; w < 8; w++) { stot += red[w]; sstot += red[8 + w]; }
    float mu  = stot * (1.f / Dq);
    float var = sstot * (1.f / Dq) - mu * mu;
    float inv = rsqrtf(var + LN_EPS);
    float4 gg = ((const float4*)g)[t];
    float4 bb = ((const float4*)b)[t];
    __half2 p0 = __floats2half2_rn((v.x - mu) * inv * gg.x + bb.x,
                                   (v.y - mu) * inv * gg.y + bb.y);
    __half2 p1 = __floats2half2_rn((v.z - mu) * inv * gg.z + bb.z,
                                   (v.w - mu) * inv * gg.w + bb.w);
    long base = (long)row * Dq + t * 4;
    *(__half2*)(o + base)     = p0;
    *(__half2*)(o + base + 2) = p1;
}

// ---------------------------------------------------------------------------
// fp16 GEMM: C = A @ (Bhi [+ Blo]).  A fp16 [M][K], B fp16 [N][K] (transposed).
// NB = number of B terms (1 or 2). Tile 128x256, 8 warps (2x4), warp 64x64,
// 3-stage cp.async, ldmatrix.x4 fragments, 1 barrier per K-step.
// EPI: 2 +bias+residual fp32; 3 +bias+relu -> fp16; 4 -> fp16 hi/lo w/ q prescale
// ---------------------------------------------------------------------------
#define KPAD 40
#define AST (128 * KPAD)
#define BST (256 * KPAD)

template <int EPI, int NB>
__global__ void __launch_bounds__(256, 1)
gemm_f16(const __half* __restrict__ A,
         const __half* __restrict__ Bhi,
         const __half* __restrict__ Blo,
         const float* __restrict__ bias,
         const float* __restrict__ res,
         float* __restrict__ C,
         __half* __restrict__ Chi,
         __half* __restrict__ Clo,
         __half* __restrict__ Ch,
         int N, int K)
{
    constexpr int STAGE = AST + NB * BST;
    extern __shared__ __half smem[];
    const int tid  = threadIdx.x;
    const int lane = tid & 31;
    const int warp = tid >> 5;
    const int wm = warp >> 2;
    const int wn = warp & 3;
    const int a_r = lane & 15;
    const int a_c = (lane >> 4) << 3;
    const int b_r = (lane & 7) + ((lane >> 4) << 3);
    const int b_c = ((lane >> 3) & 1) << 3;

    const int bm = blockIdx.y, bn = blockIdx.x;
    const __half* A_b   = A   + (long)bm * 128 * K;
    const __half* Bhi_b = Bhi + (long)bn * 256 * K;
    const __half* Blo_b = (NB == 2) ? Blo + (long)bn * 256 * K : nullptr;

    auto sA  = [&](int st) -> __half* { return smem + st * STAGE; };
    auto sBh = [&](int st) -> __half* { return smem + st * STAGE + AST; };
    auto sBl = [&](int st) -> __half* { return smem + st * STAGE + AST + BST; };

    auto ld_stage = [&](int st, int kt) {
        long k0 = (long)kt * 32;
        #pragma unroll
        for (int i = 0; i < 2; i++) {
            int c = tid + i * 256;
            int row = c >> 2, ch = (c & 3) * 8;
            cp16(sA(st) + row * KPAD + ch, A_b + (long)row * K + k0 + ch);
        }
        #pragma unroll
        for (int i = 0; i < 4; i++) {
            int c = tid + i * 256;
            int row = c >> 2, ch = (c & 3) * 8;
            long go = (long)row * K + k0 + ch;
            int  so = row * KPAD + ch;
            cp16(sBh(st) + so, Bhi_b + go);
            if (NB == 2) cp16(sBl(st) + so, Blo_b + go);
        }
    };

    float acc[4][8][4];
    #pragma unroll
    for (int i = 0; i < 4; i++)
        #pragma unroll
        for (int j = 0; j < 8; j++)
            #pragma unroll
            for (int r = 0; r < 4; r++) acc[i][j][r] = 0.f;

    const int KT = K / 32;
    ld_stage(0, 0); CP_COMMIT();
    ld_stage(1, 1); CP_COMMIT();

    int st = 0;
    for (int kt = 0; kt < KT; kt++) {
        if (kt + 1 < KT) { CP_WAIT1(); } else { CP_WAIT0(); }
        __syncthreads();
        if (kt + 2 < KT) {
            int wst = st + 2; if (wst >= 3) wst -= 3;
            ld_stage(wst, kt + 2);
            CP_COMMIT();
        }

        const __half* pA  = sA(st);
        const __half* pBh = sBh(st);
        const __half* pBl = sBl(st);

        #pragma unroll
        for (int ks = 0; ks < 2; ks++) {
            const int k16 = ks * 16;
            uint32_t af[4][4], bh[8][2], bl[8][2];
            #pragma unroll
            for (int mt = 0; mt < 4; mt++)
                ldmx4(af[mt], pA + (wm * 64 + mt * 16 + a_r) * KPAD + k16 + a_c);
            #pragma unroll
            for (int np = 0; np < 4; np++) {
                int row = wn * 64 + np * 16 + b_r;
                uint32_t r[4];
                ldmx4(r, pBh + row * KPAD + k16 + b_c);
                bh[2*np][0] = r[0]; bh[2*np][1] = r[1];
                bh[2*np+1][0] = r[2]; bh[2*np+1][1] = r[3];
                if (NB == 2) {
                    ldmx4(r, pBl + row * KPAD + k16 + b_c);
                    bl[2*np][0] = r[0]; bl[2*np][1] = r[1];
                    bl[2*np+1][0] = r[2]; bl[2*np+1][1] = r[3];
                }
            }
            #pragma unroll
            for (int mt = 0; mt < 4; mt++)
                #pragma unroll
                for (int nt = 0; nt < 8; nt++) {
                    mma_f16(acc[mt][nt], af[mt], bh[nt]);
                    if (NB == 2) mma_f16(acc[mt][nt], af[mt], bl[nt]);
                }
        }
        if (++st == 3) st = 0;
    }

    // epilogue
    const int lr4 = lane >> 2;
    const int lc2 = (lane & 3) * 2;
    #pragma unroll
    for (int mt = 0; mt < 4; mt++) {
        #pragma unroll
        for (int nt = 0; nt < 8; nt++) {
            int c = bn * 256 + wn * 64 + nt * 8 + lc2;
            #pragma unroll
            for (int half = 0; half < 2; half++) {
                int r = bm * 128 + wm * 64 + mt * 16 + lr4 + half * 8;
                float v0 = acc[mt][nt][half * 2 + 0];
                float v1 = acc[mt][nt][half * 2 + 1];
                long off = (long)r * N + c;
                if (EPI == 2) {
                    float2 bv = *(const float2*)(bias + c);
                    float2 rv = *(const float2*)(res + off);
                    *(float2*)(C + off) = make_float2(v0 + bv.x + rv.x,
                                                      v1 + bv.y + rv.y);
                } else if (EPI == 3) {
                    float2 bv = *(const float2*)(bias + c);
                    v0 = fmaxf(v0 + bv.x, 0.f);
                    v1 = fmaxf(v1 + bv.y, 0.f);
                    *(__half2*)(Ch + off) = __floats2half2_rn(v0, v1);
                } else {  // EPI == 4: fp16 hi/lo, q cols prescaled
                    float scale = (c < Dq) ? ATT_SCALE : 1.f;
                    v0 *= scale; v1 *= scale;
                    __half h0 = __float2half(v0), h1 = __float2half(v1);
                    __half2 hw(h0, h1);
                    __half2 lw = __floats2half2_rn(v0 - __half2float(h0),
                                                   v1 - __half2float(h1));
                    *(__half2*)(Chi + off) = hw;
                    *(__half2*)(Clo + off) = lw;
                }
            }
        }
    }
}
#define GEMM_SMEM_NB2 (3 * (AST + 2 * BST) * 2)   // 153600 B
#define GEMM_SMEM_NB1 (3 * (AST + 1 * BST) * 2)   // 92160 B

// ---------------------------------------------------------------------------
// Flash attention, fp16 2-term: QK = Q_f16 x (Khi + Klo); PV = P_f16 x (Vhi + Vlo)
// Block: 128 Q rows x (b,h); 8 warps x 16 rows; KV tile 64, double buffered.
// ---------------------------------------------------------------------------
#define FPAD 72
#define FLASH_SMEM ((128 * FPAD + 2 * 4 * 64 * FPAD) * 2)   // 92160 B

__global__ void __launch_bounds__(256)
flash_tc(const __half* __restrict__ qkvh,
         const __half* __restrict__ qkvl,
         __half* __restrict__ outp)
{
    extern __shared__ __half sm[];
    __half* QH = sm;                       // single Q plane (fp16)

    const int qi  = gridDim.x - 1 - blockIdx.x;
    const int bh  = blockIdx.y;
    const int b   = bh >> 4;
    const int h   = bh & 15;
    const int tid  = threadIdx.x;
    const int lane = tid & 31;
    const int warp = tid >> 5;
    const int g  = lane >> 2;
    const int t2 = (lane & 3) * 2;
    const int a_r = lane & 15;
    const int a_c = (lane >> 4) << 3;
    const int b_r = (lane & 7) + ((lane >> 4) << 3);
    const int b_c = ((lane >> 3) & 1) << 3;

    const long rb = (long)b * Tq;
    const __half* qh = qkvh + (rb + qi * 128) * (3 * Dq) + h * HDq;
    const __half* kh = qkvh + rb * (3 * Dq) + Dq + h * HDq;
    const __half* kl = qkvl + rb * (3 * Dq) + Dq + h * HDq;
    const __half* vh = qkvh + rb * (3 * Dq) + 2 * Dq + h * HDq;
    const __half* vl = qkvl + rb * (3 * Dq) + 2 * Dq + h * HDq;

    auto kvbase = [&](int st) -> __half* {
        return sm + 128 * FPAD + st * (4 * 64 * FPAD);
    };
    auto ldkv = [&](int st, int jt) {
        __half* KB = kvbase(st);
        #pragma unroll
        for (int i = 0; i < 2; i++) {
            int c = tid + i * 256;
            int row = c >> 3;
            int c8 = (c & 7) * 8;
            long go = (long)(jt * 64 + row) * (3 * Dq) + c8;
            int so = row * FPAD + c8;
            cp16(KB + so,                 kh + go);
            cp16(KB + 64 * FPAD + so,     kl + go);
            cp16(KB + 2 * 64 * FPAD + so, vh + go);
            cp16(KB + 3 * 64 * FPAD + so, vl + go);
        }
    };

    #pragma unroll
    for (int i = 0; i < 4; i++) {
        int c = tid + i * 256;
        int row = c >> 3;
        int c8 = (c & 7) * 8;
        cp16(QH + row * FPAD + c8, qh + (long)row * (3 * Dq) + c8);
    }
    ldkv(0, 0);
    CP_COMMIT();

    float oacc[8][4];
    #pragma unroll
    for (int nt = 0; nt < 8; nt++)
        #pragma unroll
        for (int e = 0; e < 4; e++) oacc[nt][e] = 0.f;
    float m0 = -1e30f, m1 = -1e30f, l0 = 0.f, l1 = 0.f;

    uint32_t qf[4][4];
    const int qrow0 = qi * 128 + warp * 16 + g;
    const int jmax = 2 * qi + 1;

    for (int jt = 0; jt <= jmax; jt++) {
        CP_WAIT0();
        __syncthreads();
        if (jt < jmax) { ldkv((jt + 1) & 1, jt + 1); CP_COMMIT(); }

        if (jt == 0) {
            #pragma unroll
            for (int kt = 0; kt < 4; kt++)
                ldmx4(qf[kt], QH + (warp * 16 + a_r) * FPAD + kt * 16 + a_c);
        }

        if (jt * 64 <= qi * 128 + warp * 16 + 15) {
            __half* KB = kvbase(jt & 1);
            const __half* KHs = KB;
            const __half* KLs = KB + 64 * FPAD;
            const __half* VHs = KB + 2 * 64 * FPAD;
            const __half* VLs = KB + 3 * 64 * FPAD;

            float sacc[8][4];
            #pragma unroll
            for (int nt = 0; nt < 8; nt++)
                #pragma unroll
                for (int e = 0; e < 4; e++) sacc[nt][e] = 0.f;

            #pragma unroll
            for (int kt = 0; kt < 4; kt++) {
                uint32_t bh2[8][2], bl2[8][2];
                #pragma unroll
                for (int np = 0; np < 4; np++) {
                    int row = np * 16 + b_r;
                    uint32_t r[4];
                    ldmx4(r, KHs + row * FPAD + kt * 16 + b_c);
                    bh2[2*np][0] = r[0]; bh2[2*np][1] = r[1];
                    bh2[2*np+1][0] = r[2]; bh2[2*np+1][1] = r[3];
                    ldmx4(r, KLs + row * FPAD + kt * 16 + b_c);
                    bl2[2*np][0] = r[0]; bl2[2*np][1] = r[1];
                    bl2[2*np+1][0] = r[2]; bl2[2*np+1][1] = r[3];
                }
                #pragma unroll
                for (int nt = 0; nt < 8; nt++) {
                    mma_f16(sacc[nt], qf[kt], bh2[nt]);
                    mma_f16(sacc[nt], qf[kt], bl2[nt]);
                }
            }

            if (jt * 64 + 63 > qrow0) {
                #pragma unroll
                for (int nt = 0; nt < 8; nt++) {
                    int key0 = jt * 64 + nt * 8 + t2;
                    if (key0     > qrow0)     sacc[nt][0] = -1e30f;
                    if (key0 + 1 > qrow0)     sacc[nt][1] = -1e30f;
                    if (key0     > qrow0 + 8) sacc[nt][2] = -1e30f;
                    if (key0 + 1 > qrow0 + 8) sacc[nt][3] = -1e30f;
                }
            }

            float mx0 = -1e30f, mx1 = -1e30f;
            #pragma unroll
            for (int nt = 0; nt < 8; nt++) {
                mx0 = fmaxf(mx0, fmaxf(sacc[nt][0], sacc[nt][1]));
                mx1 = fmaxf(mx1, fmaxf(sacc[nt][2], sacc[nt][3]));
            }
            mx0 = fmaxf(mx0, __shfl_xor_sync(0xffffffffu, mx0, 1));
            mx0 = fmaxf(mx0, __shfl_xor_sync(0xffffffffu, mx0, 2));
            mx1 = fmaxf(mx1, __shfl_xor_sync(0xffffffffu, mx1, 1));
            mx1 = fmaxf(mx1, __shfl_xor_sync(0xffffffffu, mx1, 2));
            float mn0 = fmaxf(m0, mx0), mn1 = fmaxf(m1, mx1);
            float a0 = __expf(m0 - mn0), a1 = __expf(m1 - mn1);
            m0 = mn0; m1 = mn1;
            float rs0 = 0.f, rs1 = 0.f;
            #pragma unroll
            for (int nt = 0; nt < 8; nt++) {
                sacc[nt][0] = __expf(sacc[nt][0] - mn0); rs0 += sacc[nt][0];
                sacc[nt][1] = __expf(sacc[nt][1] - mn0); rs0 += sacc[nt][1];
                sacc[nt][2] = __expf(sacc[nt][2] - mn1); rs1 += sacc[nt][2];
                sacc[nt][3] = __expf(sacc[nt][3] - mn1); rs1 += sacc[nt][3];
            }
            rs0 += __shfl_xor_sync(0xffffffffu, rs0, 1);
            rs0 += __shfl_xor_sync(0xffffffffu, rs0, 2);
            rs1 += __shfl_xor_sync(0xffffffffu, rs1, 1);
            rs1 += __shfl_xor_sync(0xffffffffu, rs1, 2);
            l0 = l0 * a0 + rs0;
            l1 = l1 * a1 + rs1;
            #pragma unroll
            for (int nt = 0; nt < 8; nt++) {
                oacc[nt][0] *= a0; oacc[nt][1] *= a0;
                oacc[nt][2] *= a1; oacc[nt][3] *= a1;
            }

            #pragma unroll
            for (int j = 0; j < 4; j++) {
                uint32_t ph[4];
                ph[0] = packh2(sacc[2*j][0],   sacc[2*j][1]);
                ph[1] = packh2(sacc[2*j][2],   sacc[2*j][3]);
                ph[2] = packh2(sacc[2*j+1][0], sacc[2*j+1][1]);
                ph[3] = packh2(sacc[2*j+1][2], sacc[2*j+1][3]);
                #pragma unroll
                for (int nt = 0; nt < 8; nt++) {
                    uint32_t vhf[2], vlf[2];
                    ldmx2t(vhf[0], vhf[1], VHs + (j * 16 + (lane & 15)) * FPAD + nt * 8);
                    ldmx2t(vlf[0], vlf[1], VLs + (j * 16 + (lane & 15)) * FPAD + nt * 8);
                    mma_f16(oacc[nt], ph, vhf);
                    mma_f16(oacc[nt], ph, vlf);
                }
            }
        }
    }

    float inv0 = 1.f / l0, inv1 = 1.f / l1;
    long row0 = (long)b * Tq + qi * 128 + warp * 16 + g;
    #pragma unroll
    for (int nt = 0; nt < 8; nt++) {
        int col = h * HDq + nt * 8 + t2;
        *(__half2*)(outp + row0 * Dq + col) =
            __floats2half2_rn(oacc[nt][0] * inv0, oacc[nt][1] * inv0);
        *(__half2*)(outp + (row0 + 8) * Dq + col) =
            __floats2half2_rn(oacc[nt][2] * inv1, oacc[nt][3] * inv1);
    }
}

// ---------------------------------------------------------------------------
// Launch
// ---------------------------------------------------------------------------
extern "C" void kernel_launch(void* const* d_in, const int* in_sizes, int n_in,
                              void* d_out, int out_size)
{
    const float* x   = (const float*)d_in[0];
    const float* Wq  = (const float*)d_in[1];
    const float* Wk  = (const float*)d_in[2];
    const float* Wv  = (const float*)d_in[3];
    const float* Wp  = (const float*)d_in[4];
    const float* bp  = (const float*)d_in[5];
    const float* W1  = (const float*)d_in[6];
    const float* b1  = (const float*)d_in[7];
    const float* W2  = (const float*)d_in[8];
    const float* b2  = (const float*)d_in[9];
    const float* g1  = (const float*)d_in[10];
    const float* be1 = (const float*)d_in[11];
    const float* g2  = (const float*)d_in[12];
    const float* be2 = (const float*)d_in[13];
    float* out = (float*)d_out;

    __half *p_h, *p_wqkv_hi, *p_wqkv_lo, *p_wp_hi, *p_wp_lo;
    __half *p_w1, *p_w2, *p_attn, *p_ff, *p_qkvh, *p_qkvl;
    float *p_x1;
    cudaGetSymbolAddress((void**)&p_h,       g_h);
    cudaGetSymbolAddress((void**)&p_wqkv_hi, g_wqkv_hi);
    cudaGetSymbolAddress((void**)&p_wqkv_lo, g_wqkv_lo);
    cudaGetSymbolAddress((void**)&p_wp_hi,   g_wp_hi);
    cudaGetSymbolAddress((void**)&p_wp_lo,   g_wp_lo);
    cudaGetSymbolAddress((void**)&p_w1,      g_w1);
    cudaGetSymbolAddress((void**)&p_w2,      g_w2);
    cudaGetSymbolAddress((void**)&p_qkvh,    g_qkvh);
    cudaGetSymbolAddress((void**)&p_qkvl,    g_qkvl);
    cudaGetSymbolAddress((void**)&p_attn,    g_attn);
    cudaGetSymbolAddress((void**)&p_x1,      g_x1);
    cudaGetSymbolAddress((void**)&p_ff,      g_ff);

    cudaFuncSetAttribute(gemm_f16<4,2>, cudaFuncAttributeMaxDynamicSharedMemorySize, GEMM_SMEM_NB2);
    cudaFuncSetAttribute(gemm_f16<2,2>, cudaFuncAttributeMaxDynamicSharedMemorySize, GEMM_SMEM_NB2);
    cudaFuncSetAttribute(gemm_f16<3,1>, cudaFuncAttributeMaxDynamicSharedMemorySize, GEMM_SMEM_NB1);
    cudaFuncSetAttribute(gemm_f16<2,1>, cudaFuncAttributeMaxDynamicSharedMemorySize, GEMM_SMEM_NB1);
    cudaFuncSetAttribute(flash_tc,      cudaFuncAttributeMaxDynamicSharedMemorySize, FLASH_SMEM);

    // weight prep
    prep_wqkv_tiled<<<dim3(HDq / 32, Dq / 32, 48), dim3(32, 8)>>>(Wq, Wk, Wv, p_wqkv_hi, p_wqkv_lo);
    transpose_split_t<<<dim3(Dq / 32, Dq / 32),  dim3(32, 8)>>>(Wp, p_wp_hi, p_wp_lo, Dq, Dq);
    transpose_split_t<<<dim3(DFF / 32, Dq / 32), dim3(32, 8)>>>(W1, p_w1, nullptr, Dq, DFF);
    transpose_split_t<<<dim3(Dq / 32, DFF / 32), dim3(32, 8)>>>(W2, p_w2, nullptr, DFF, Dq);

    // LN1 -> fp16
    ln_f16<<<Mq, 256>>>(x, g1, be1, p_h);
    // QKV projection (2-term weights) -> fp16 hi/lo, q prescaled
    gemm_f16<4,2><<<dim3(3 * Dq / 256, Mq / 128), 256, GEMM_SMEM_NB2>>>(
        p_h, p_wqkv_hi, p_wqkv_lo, nullptr, nullptr,
        nullptr, p_qkvh, p_qkvl, nullptr, 3 * Dq, Dq);
    // flash attention (fp16 2-term) -> fp16
    flash_tc<<<dim3(Tq / 128, Bq * Hq), 256, FLASH_SMEM>>>(p_qkvh, p_qkvl, p_attn);
    // output projection (2-term) + bias + residual(x)
    gemm_f16<2,2><<<dim3(Dq / 256, Mq / 128), 256, GEMM_SMEM_NB2>>>(
        p_attn, p_wp_hi, p_wp_lo, bp, x,
        p_x1, nullptr, nullptr, nullptr, Dq, Dq);
    // LN2 -> fp16
    ln_f16<<<Mq, 256>>>(p_x1, g2, be2, p_h);
    // FFN up (single-weight) + bias + relu -> fp16
    gemm_f16<3,1><<<dim3(DFF / 256, Mq / 128), 256, GEMM_SMEM_NB1>>>(
        p_h, p_w1, nullptr, b1, nullptr,
        nullptr, nullptr, nullptr, p_ff, DFF, Dq);
    // FFN down (single-weight) + bias + residual(x1) -> d_out
    gemm_f16<2,1><<<dim3(Dq / 256, Mq / 128), 256, GEMM_SMEM_NB1>>>(
        p_ff, p_w2, nullptr, b2, p_x1,
        out, nullptr, nullptr, nullptr, Dq, DFF);
}

// round 10
// speedup vs baseline: 2.7833x; 1.3091x over previous
#include <cuda_runtime.h>
#include <cuda_fp16.h>
#include <stdint.h>

// Problem constants
#define Bq   4
#define Tq   2048
#define Dq   1024
#define Hq   16
#define HDq  64
#define Mq   (Bq * Tq)        // 8192
#define DFF  (4 * Dq)         // 4096
#define LN_EPS 1e-5f
#define ATT_SCALE 0.125f

// ---------------------------------------------------------------------------
// Scratch
// ---------------------------------------------------------------------------
__device__ __half g_h[Mq * Dq];            // LN out fp16
__device__ __half g_wqkv[3*Dq*Dq];         // [3D][D] fp16
__device__ __half g_wp[Dq*Dq];             // [D][D] transposed fp16
__device__ __half g_w1[DFF*Dq];            // [4D][D] fp16
__device__ __half g_w2[Dq*DFF];            // [D][4D] fp16
__device__ __half g_qkv[Mq * 3 * Dq];      // q pre-scaled, fp16
__device__ __half g_attn[Mq * Dq];         // flash out fp16
__device__ float  g_x1[Mq * Dq];
__device__ __half g_ff[Mq * DFF];          // FFN hidden fp16

// ---------------------------------------------------------------------------
// Helpers
// ---------------------------------------------------------------------------
__device__ __forceinline__ uint32_t packh2(float x, float y) {
    __half2 h = __floats2half2_rn(x, y);
    return *reinterpret_cast<uint32_t*>(&h);
}

__device__ __forceinline__ void mma_f16(float* c, const uint32_t* a, const uint32_t* b) {
    asm volatile(
        "mma.sync.aligned.m16n8k16.row.col.f32.f16.f16.f32 "
        "{%0,%1,%2,%3}, {%4,%5,%6,%7}, {%8,%9}, {%0,%1,%2,%3};"
        : "+f"(c[0]), "+f"(c[1]), "+f"(c[2]), "+f"(c[3])
        : "r"(a[0]), "r"(a[1]), "r"(a[2]), "r"(a[3]), "r"(b[0]), "r"(b[1]));
}

__device__ __forceinline__ void ldmx4(uint32_t* r, const void* p) {
    uint32_t a = (uint32_t)__cvta_generic_to_shared(p);
    asm volatile("ldmatrix.sync.aligned.m8n8.x4.shared.b16 {%0,%1,%2,%3}, [%4];"
                 : "=r"(r[0]), "=r"(r[1]), "=r"(r[2]), "=r"(r[3]) : "r"(a));
}

__device__ __forceinline__ void ldmx2t(uint32_t& r0, uint32_t& r1, const void* p) {
    uint32_t a = (uint32_t)__cvta_generic_to_shared(p);
    asm volatile("ldmatrix.sync.aligned.m8n8.x2.trans.shared.b16 {%0,%1}, [%2];"
                 : "=r"(r0), "=r"(r1) : "r"(a));
}

__device__ __forceinline__ void cp16(void* sdst, const void* gsrc) {
    unsigned sa = (unsigned)__cvta_generic_to_shared(sdst);
    asm volatile("cp.async.cg.shared.global [%0], [%1], 16;" :: "r"(sa), "l"(gsrc));
}
#define CP_COMMIT() asm volatile("cp.async.commit_group;")
#define CP_WAIT0()  asm volatile("cp.async.wait_group 0;")
#define CP_WAIT1()  asm volatile("cp.async.wait_group 1;")

// ---------------------------------------------------------------------------
// Weight prep (single fp16 outputs)
// ---------------------------------------------------------------------------
__global__ void prep_wqkv_tiled(const float* __restrict__ Wq,
                                const float* __restrict__ Wk,
                                const float* __restrict__ Wv,
                                __half* __restrict__ o)
{
    __shared__ float t[32][33];
    int s = blockIdx.z >> 4, h = blockIdx.z & 15;
    const float* W = (s == 0) ? Wq : (s == 1) ? Wk : Wv;
    const float* in = W + (long)h * Dq * HDq;
    int d0 = blockIdx.y * 32, hd0 = blockIdx.x * 32;
    int tx = threadIdx.x, ty = threadIdx.y;
    #pragma unroll
    for (int i = 0; i < 32; i += 8)
        t[ty + i][tx] = in[(long)(d0 + ty + i) * HDq + hd0 + tx];
    __syncthreads();
    long nrow = (long)s * Dq + h * HDq + hd0;
    #pragma unroll
    for (int i = 0; i < 32; i += 8)
        o[(nrow + ty + i) * Dq + d0 + tx] = __float2half(t[tx][ty + i]);
}

// in: [K][N] fp32 -> out: [N][K] fp16
__global__ void transpose_f16(const float* __restrict__ in,
                              __half* __restrict__ o,
                              int K, int N)
{
    __shared__ float t[32][33];
    int k0 = blockIdx.y * 32, n0 = blockIdx.x * 32;
    int tx = threadIdx.x, ty = threadIdx.y;
    #pragma unroll
    for (int i = 0; i < 32; i += 8)
        t[ty + i][tx] = in[(long)(k0 + ty + i) * N + n0 + tx];
    __syncthreads();
    #pragma unroll
    for (int i = 0; i < 32; i += 8)
        o[(long)(n0 + ty + i) * K + k0 + tx] = __float2half(t[tx][ty + i]);
}

// ---------------------------------------------------------------------------
// LayerNorm -> fp16
// ---------------------------------------------------------------------------
__global__ void ln_f16(const float* __restrict__ x,
                       const float* __restrict__ g,
                       const float* __restrict__ b,
                       __half* __restrict__ o)
{
    __shared__ float red[16];
    int row = blockIdx.x;
    int t = threadIdx.x;
    const float4* xr = (const float4*)(x + (long)row * Dq);
    float4 v = xr[t];
    float s  = v.x + v.y + v.z + v.w;
    float ss = v.x * v.x + v.y * v.y + v.z * v.z + v.w * v.w;
    #pragma unroll
    for (int o2 = 16; o2 >= 1; o2 >>= 1) {
        s  += __shfl_xor_sync(0xffffffffu, s,  o2);
        ss += __shfl_xor_sync(0xffffffffu, ss, o2);
    }
    if ((t & 31) == 0) { red[t >> 5] = s; red[8 + (t >> 5)] = ss; }
    __syncthreads();
    float stot = 0.f, sstot = 0.f;
    #pragma unroll
    for (int w = 0; w < 8; w++) { stot += red[w]; sstot += red[8 + w]; }
    float mu  = stot * (1.f / Dq);
    float var = sstot * (1.f / Dq) - mu * mu;
    float inv = rsqrtf(var + LN_EPS);
    float4 gg = ((const float4*)g)[t];
    float4 bb = ((const float4*)b)[t];
    __half2 p0 = __floats2half2_rn((v.x - mu) * inv * gg.x + bb.x,
                                   (v.y - mu) * inv * gg.y + bb.y);
    __half2 p1 = __floats2half2_rn((v.z - mu) * inv * gg.z + bb.z,
                                   (v.w - mu) * inv * gg.w + bb.w);
    long base = (long)row * Dq + t * 4;
    *(__half2*)(o + base)     = p0;
    *(__half2*)(o + base + 2) = p1;
}

// ---------------------------------------------------------------------------
// Plain fp16 GEMM: C = A @ B.  A fp16 [M][K], B fp16 [N][K] (transposed).
// Tile 128x256, 8 warps (2x4), warp 64x64, 3-stage cp.async, ldmatrix.x4.
// EPI: 2 +bias+residual fp32; 3 +bias+relu -> fp16; 4 -> fp16 w/ q prescale
// ---------------------------------------------------------------------------
#define KPAD 40
#define AST (128 * KPAD)
#define BST (256 * KPAD)
#define STAGE (AST + BST)
#define GEMM_SMEM (3 * STAGE * 2)   // 92160 B

template <int EPI>
__global__ void __launch_bounds__(256, 1)
gemm_f16(const __half* __restrict__ A,
         const __half* __restrict__ B,
         const float* __restrict__ bias,
         const float* __restrict__ res,
         float* __restrict__ C,
         __half* __restrict__ Ch,
         int N, int K)
{
    extern __shared__ __half smem[];
    const int tid  = threadIdx.x;
    const int lane = tid & 31;
    const int warp = tid >> 5;
    const int wm = warp >> 2;
    const int wn = warp & 3;
    const int a_r = lane & 15;
    const int a_c = (lane >> 4) << 3;
    const int b_r = (lane & 7) + ((lane >> 4) << 3);
    const int b_c = ((lane >> 3) & 1) << 3;

    const int bm = blockIdx.y, bn = blockIdx.x;
    const __half* A_b = A + (long)bm * 128 * K;
    const __half* B_b = B + (long)bn * 256 * K;

    auto sA = [&](int st) -> __half* { return smem + st * STAGE; };
    auto sB = [&](int st) -> __half* { return smem + st * STAGE + AST; };

    auto ld_stage = [&](int st, int kt) {
        long k0 = (long)kt * 32;
        #pragma unroll
        for (int i = 0; i < 2; i++) {
            int c = tid + i * 256;
            int row = c >> 2, ch = (c & 3) * 8;
            cp16(sA(st) + row * KPAD + ch, A_b + (long)row * K + k0 + ch);
        }
        #pragma unroll
        for (int i = 0; i < 4; i++) {
            int c = tid + i * 256;
            int row = c >> 2, ch = (c & 3) * 8;
            cp16(sB(st) + row * KPAD + ch, B_b + (long)row * K + k0 + ch);
        }
    };

    float acc[4][8][4];
    #pragma unroll
    for (int i = 0; i < 4; i++)
        #pragma unroll
        for (int j = 0; j < 8; j++)
            #pragma unroll
            for (int r = 0; r < 4; r++) acc[i][j][r] = 0.f;

    const int KT = K / 32;
    ld_stage(0, 0); CP_COMMIT();
    ld_stage(1, 1); CP_COMMIT();

    int st = 0;
    for (int kt = 0; kt < KT; kt++) {
        if (kt + 1 < KT) { CP_WAIT1(); } else { CP_WAIT0(); }
        __syncthreads();
        if (kt + 2 < KT) {
            int wst = st + 2; if (wst >= 3) wst -= 3;
            ld_stage(wst, kt + 2);
            CP_COMMIT();
        }

        const __half* pA = sA(st);
        const __half* pB = sB(st);

        #pragma unroll
        for (int ks = 0; ks < 2; ks++) {
            const int k16 = ks * 16;
            uint32_t af[4][4], bf[8][2];
            #pragma unroll
            for (int mt = 0; mt < 4; mt++)
                ldmx4(af[mt], pA + (wm * 64 + mt * 16 + a_r) * KPAD + k16 + a_c);
            #pragma unroll
            for (int np = 0; np < 4; np++) {
                int row = wn * 64 + np * 16 + b_r;
                uint32_t r[4];
                ldmx4(r, pB + row * KPAD + k16 + b_c);
                bf[2*np][0] = r[0]; bf[2*np][1] = r[1];
                bf[2*np+1][0] = r[2]; bf[2*np+1][1] = r[3];
            }
            #pragma unroll
            for (int mt = 0; mt < 4; mt++)
                #pragma unroll
                for (int nt = 0; nt < 8; nt++)
                    mma_f16(acc[mt][nt], af[mt], bf[nt]);
        }
        if (++st == 3) st = 0;
    }

    // epilogue
    const int lr4 = lane >> 2;
    const int lc2 = (lane & 3) * 2;
    #pragma unroll
    for (int mt = 0; mt < 4; mt++) {
        #pragma unroll
        for (int nt = 0; nt < 8; nt++) {
            int c = bn * 256 + wn * 64 + nt * 8 + lc2;
            #pragma unroll
            for (int half = 0; half < 2; half++) {
                int r = bm * 128 + wm * 64 + mt * 16 + lr4 + half * 8;
                float v0 = acc[mt][nt][half * 2 + 0];
                float v1 = acc[mt][nt][half * 2 + 1];
                long off = (long)r * N + c;
                if (EPI == 2) {
                    float2 bv = *(const float2*)(bias + c);
                    float2 rv = *(const float2*)(res + off);
                    *(float2*)(C + off) = make_float2(v0 + bv.x + rv.x,
                                                      v1 + bv.y + rv.y);
                } else if (EPI == 3) {
                    float2 bv = *(const float2*)(bias + c);
                    v0 = fmaxf(v0 + bv.x, 0.f);
                    v1 = fmaxf(v1 + bv.y, 0.f);
                    *(__half2*)(Ch + off) = __floats2half2_rn(v0, v1);
                } else {  // EPI == 4: fp16, q cols prescaled
                    float scale = (c < Dq) ? ATT_SCALE : 1.f;
                    *(__half2*)(Ch + off) = __floats2half2_rn(v0 * scale, v1 * scale);
                }
            }
        }
    }
}

// ---------------------------------------------------------------------------
// Flash attention, plain fp16: QK = Q x K; PV = P x V (fp32 accum).
// Block: 128 Q rows x (b,h); 8 warps x 16 rows; KV tile 64, double buffered.
// ---------------------------------------------------------------------------
#define FPAD 72
#define FLASH_SMEM ((128 * FPAD + 2 * 2 * 64 * FPAD) * 2)   // 55296 B

__global__ void __launch_bounds__(256)
flash_tc(const __half* __restrict__ qkv,
         __half* __restrict__ outp)
{
    extern __shared__ __half sm[];
    __half* QH = sm;

    const int qi  = gridDim.x - 1 - blockIdx.x;
    const int bh  = blockIdx.y;
    const int b   = bh >> 4;
    const int h   = bh & 15;
    const int tid  = threadIdx.x;
    const int lane = tid & 31;
    const int warp = tid >> 5;
    const int g  = lane >> 2;
    const int t2 = (lane & 3) * 2;
    const int a_r = lane & 15;
    const int a_c = (lane >> 4) << 3;
    const int b_r = (lane & 7) + ((lane >> 4) << 3);
    const int b_c = ((lane >> 3) & 1) << 3;

    const long rb = (long)b * Tq;
    const __half* qp = qkv + (rb + qi * 128) * (3 * Dq) + h * HDq;
    const __half* kp = qkv + rb * (3 * Dq) + Dq + h * HDq;
    const __half* vp = qkv + rb * (3 * Dq) + 2 * Dq + h * HDq;

    auto kvbase = [&](int st) -> __half* {
        return sm + 128 * FPAD + st * (2 * 64 * FPAD);
    };
    auto ldkv = [&](int st, int jt) {
        __half* KB = kvbase(st);
        #pragma unroll
        for (int i = 0; i < 2; i++) {
            int c = tid + i * 256;
            int row = c >> 3;
            int c8 = (c & 7) * 8;
            long go = (long)(jt * 64 + row) * (3 * Dq) + c8;
            int so = row * FPAD + c8;
            cp16(KB + so,             kp + go);
            cp16(KB + 64 * FPAD + so, vp + go);
        }
    };

    #pragma unroll
    for (int i = 0; i < 4; i++) {
        int c = tid + i * 256;
        int row = c >> 3;
        int c8 = (c & 7) * 8;
        cp16(QH + row * FPAD + c8, qp + (long)row * (3 * Dq) + c8);
    }
    ldkv(0, 0);
    CP_COMMIT();

    float oacc[8][4];
    #pragma unroll
    for (int nt = 0; nt < 8; nt++)
        #pragma unroll
        for (int e = 0; e < 4; e++) oacc[nt][e] = 0.f;
    float m0 = -1e30f, m1 = -1e30f, l0 = 0.f, l1 = 0.f;

    uint32_t qf[4][4];
    const int qrow0 = qi * 128 + warp * 16 + g;
    const int jmax = 2 * qi + 1;

    for (int jt = 0; jt <= jmax; jt++) {
        CP_WAIT0();
        __syncthreads();
        if (jt < jmax) { ldkv((jt + 1) & 1, jt + 1); CP_COMMIT(); }

        if (jt == 0) {
            #pragma unroll
            for (int kt = 0; kt < 4; kt++)
                ldmx4(qf[kt], QH + (warp * 16 + a_r) * FPAD + kt * 16 + a_c);
        }

        if (jt * 64 <= qi * 128 + warp * 16 + 15) {
            __half* KB = kvbase(jt & 1);
            const __half* KHs = KB;
            const __half* VHs = KB + 64 * FPAD;

            float sacc[8][4];
            #pragma unroll
            for (int nt = 0; nt < 8; nt++)
                #pragma unroll
                for (int e = 0; e < 4; e++) sacc[nt][e] = 0.f;

            #pragma unroll
            for (int kt = 0; kt < 4; kt++) {
                uint32_t bf[8][2];
                #pragma unroll
                for (int np = 0; np < 4; np++) {
                    int row = np * 16 + b_r;
                    uint32_t r[4];
                    ldmx4(r, KHs + row * FPAD + kt * 16 + b_c);
                    bf[2*np][0] = r[0]; bf[2*np][1] = r[1];
                    bf[2*np+1][0] = r[2]; bf[2*np+1][1] = r[3];
                }
                #pragma unroll
                for (int nt = 0; nt < 8; nt++)
                    mma_f16(sacc[nt], qf[kt], bf[nt]);
            }

            if (jt * 64 + 63 > qrow0) {
                #pragma unroll
                for (int nt = 0; nt < 8; nt++) {
                    int key0 = jt * 64 + nt * 8 + t2;
                    if (key0     > qrow0)     sacc[nt][0] = -1e30f;
                    if (key0 + 1 > qrow0)     sacc[nt][1] = -1e30f;
                    if (key0     > qrow0 + 8) sacc[nt][2] = -1e30f;
                    if (key0 + 1 > qrow0 + 8) sacc[nt][3] = -1e30f;
                }
            }

            float mx0 = -1e30f, mx1 = -1e30f;
            #pragma unroll
            for (int nt = 0; nt < 8; nt++) {
                mx0 = fmaxf(mx0, fmaxf(sacc[nt][0], sacc[nt][1]));
                mx1 = fmaxf(mx1, fmaxf(sacc[nt][2], sacc[nt][3]));
            }
            mx0 = fmaxf(mx0, __shfl_xor_sync(0xffffffffu, mx0, 1));
            mx0 = fmaxf(mx0, __shfl_xor_sync(0xffffffffu, mx0, 2));
            mx1 = fmaxf(mx1, __shfl_xor_sync(0xffffffffu, mx1, 1));
            mx1 = fmaxf(mx1, __shfl_xor_sync(0xffffffffu, mx1, 2));
            float mn0 = fmaxf(m0, mx0), mn1 = fmaxf(m1, mx1);
            float a0 = __expf(m0 - mn0), a1 = __expf(m1 - mn1);
            m0 = mn0; m1 = mn1;
            float rs0 = 0.f, rs1 = 0.f;
            #pragma unroll
            for (int nt = 0; nt < 8; nt++) {
                sacc[nt][0] = __expf(sacc[nt][0] - mn0); rs0 += sacc[nt][0];
                sacc[nt][1] = __expf(sacc[nt][1] - mn0); rs0 += sacc[nt][1];
                sacc[nt][2] = __expf(sacc[nt][2] - mn1); rs1 += sacc[nt][2];
                sacc[nt][3] = __expf(sacc[nt][3] - mn1); rs1 += sacc[nt][3];
            }
            rs0 += __shfl_xor_sync(0xffffffffu, rs0, 1);
            rs0 += __shfl_xor_sync(0xffffffffu, rs0, 2);
            rs1 += __shfl_xor_sync(0xffffffffu, rs1, 1);
            rs1 += __shfl_xor_sync(0xffffffffu, rs1, 2);
            l0 = l0 * a0 + rs0;
            l1 = l1 * a1 + rs1;
            #pragma unroll
            for (int nt = 0; nt < 8; nt++) {
                oacc[nt][0] *= a0; oacc[nt][1] *= a0;
                oacc[nt][2] *= a1; oacc[nt][3] *= a1;
            }

            #pragma unroll
            for (int j = 0; j < 4; j++) {
                uint32_t ph[4];
                ph[0] = packh2(sacc[2*j][0],   sacc[2*j][1]);
                ph[1] = packh2(sacc[2*j][2],   sacc[2*j][3]);
                ph[2] = packh2(sacc[2*j+1][0], sacc[2*j+1][1]);
                ph[3] = packh2(sacc[2*j+1][2], sacc[2*j+1][3]);
                #pragma unroll
                for (int nt = 0; nt < 8; nt++) {
                    uint32_t vf[2];
                    ldmx2t(vf[0], vf[1], VHs + (j * 16 + (lane & 15)) * FPAD + nt * 8);
                    mma_f16(oacc[nt], ph, vf);
                }
            }
        }
    }

    float inv0 = 1.f / l0, inv1 = 1.f / l1;
    long row0 = (long)b * Tq + qi * 128 + warp * 16 + g;
    #pragma unroll
    for (int nt = 0; nt < 8; nt++) {
        int col = h * HDq + nt * 8 + t2;
        *(__half2*)(outp + row0 * Dq + col) =
            __floats2half2_rn(oacc[nt][0] * inv0, oacc[nt][1] * inv0);
        *(__half2*)(outp + (row0 + 8) * Dq + col) =
            __floats2half2_rn(oacc[nt][2] * inv1, oacc[nt][3] * inv1);
    }
}

// ---------------------------------------------------------------------------
// Launch
// ---------------------------------------------------------------------------
extern "C" void kernel_launch(void* const* d_in, const int* in_sizes, int n_in,
                              void* d_out, int out_size)
{
    const float* x   = (const float*)d_in[0];
    const float* Wq  = (const float*)d_in[1];
    const float* Wk  = (const float*)d_in[2];
    const float* Wv  = (const float*)d_in[3];
    const float* Wp  = (const float*)d_in[4];
    const float* bp  = (const float*)d_in[5];
    const float* W1  = (const float*)d_in[6];
    const float* b1  = (const float*)d_in[7];
    const float* W2  = (const float*)d_in[8];
    const float* b2  = (const float*)d_in[9];
    const float* g1  = (const float*)d_in[10];
    const float* be1 = (const float*)d_in[11];
    const float* g2  = (const float*)d_in[12];
    const float* be2 = (const float*)d_in[13];
    float* out = (float*)d_out;

    __half *p_h, *p_wqkv, *p_wp, *p_w1, *p_w2, *p_attn, *p_ff, *p_qkv;
    float *p_x1;
    cudaGetSymbolAddress((void**)&p_h,    g_h);
    cudaGetSymbolAddress((void**)&p_wqkv, g_wqkv);
    cudaGetSymbolAddress((void**)&p_wp,   g_wp);
    cudaGetSymbolAddress((void**)&p_w1,   g_w1);
    cudaGetSymbolAddress((void**)&p_w2,   g_w2);
    cudaGetSymbolAddress((void**)&p_qkv,  g_qkv);
    cudaGetSymbolAddress((void**)&p_attn, g_attn);
    cudaGetSymbolAddress((void**)&p_x1,   g_x1);
    cudaGetSymbolAddress((void**)&p_ff,   g_ff);

    cudaFuncSetAttribute(gemm_f16<2>, cudaFuncAttributeMaxDynamicSharedMemorySize, GEMM_SMEM);
    cudaFuncSetAttribute(gemm_f16<3>, cudaFuncAttributeMaxDynamicSharedMemorySize, GEMM_SMEM);
    cudaFuncSetAttribute(gemm_f16<4>, cudaFuncAttributeMaxDynamicSharedMemorySize, GEMM_SMEM);
    cudaFuncSetAttribute(flash_tc,    cudaFuncAttributeMaxDynamicSharedMemorySize, FLASH_SMEM);

    // weight prep
    prep_wqkv_tiled<<<dim3(HDq / 32, Dq / 32, 48), dim3(32, 8)>>>(Wq, Wk, Wv, p_wqkv);
    transpose_f16<<<dim3(Dq / 32, Dq / 32),  dim3(32, 8)>>>(Wp, p_wp, Dq, Dq);
    transpose_f16<<<dim3(DFF / 32, Dq / 32), dim3(32, 8)>>>(W1, p_w1, Dq, DFF);
    transpose_f16<<<dim3(Dq / 32, DFF / 32), dim3(32, 8)>>>(W2, p_w2, DFF, Dq);

    // LN1 -> fp16
    ln_f16<<<Mq, 256>>>(x, g1, be1, p_h);
    // QKV projection -> fp16, q prescaled
    gemm_f16<4><<<dim3(3 * Dq / 256, Mq / 128), 256, GEMM_SMEM>>>(
        p_h, p_wqkv, nullptr, nullptr, nullptr, p_qkv, 3 * Dq, Dq);
    // flash attention -> fp16
    flash_tc<<<dim3(Tq / 128, Bq * Hq), 256, FLASH_SMEM>>>(p_qkv, p_attn);
    // output projection + bias + residual(x)
    gemm_f16<2><<<dim3(Dq / 256, Mq / 128), 256, GEMM_SMEM>>>(
        p_attn, p_wp, bp, x, p_x1, nullptr, Dq, Dq);
    // LN2 -> fp16
    ln_f16<<<Mq, 256>>>(p_x1, g2, be2, p_h);
    // FFN up + bias + relu -> fp16
    gemm_f16<3><<<dim3(DFF / 256, Mq / 128), 256, GEMM_SMEM>>>(
        p_h, p_w1, b1, nullptr, nullptr, p_ff, DFF, Dq);
    // FFN down + bias + residual(x1) -> d_out
    gemm_f16<2><<<dim3(Dq / 256, Mq / 128), 256, GEMM_SMEM>>>(
        p_ff, p_w2, b2, p_x1, out, nullptr, Dq, DFF);
}

// round 12
// speedup vs baseline: 3.1874x; 1.1452x over previous
#include <cuda_runtime.h>
#include <cuda_fp16.h>
#include <stdint.h>

// Problem constants
#define Bq   4
#define Tq   2048
#define Dq   1024
#define Hq   16
#define HDq  64
#define Mq   (Bq * Tq)        // 8192
#define DFF  (4 * Dq)         // 4096
#define LN_EPS 1e-5f
#define ATT_SCALE 0.125f

// ---------------------------------------------------------------------------
// Scratch
// ---------------------------------------------------------------------------
__device__ __half g_h[Mq * Dq];            // LN out fp16
__device__ __half g_wqkv[3*Dq*Dq];         // [3D][D] fp16
__device__ __half g_wp[Dq*Dq];             // [D][D] transposed fp16
__device__ __half g_w1[DFF*Dq];            // [4D][D] fp16
__device__ __half g_w2[Dq*DFF];            // [D][4D] fp16
__device__ __half g_qkv[Mq * 3 * Dq];      // q pre-scaled, fp16
__device__ __half g_attn[Mq * Dq];         // flash out fp16
__device__ float  g_x1[Mq * Dq];
__device__ __half g_ff[Mq * DFF];          // FFN hidden fp16

// ---------------------------------------------------------------------------
// Helpers
// ---------------------------------------------------------------------------
__device__ __forceinline__ uint32_t packh2(float x, float y) {
    __half2 h = __floats2half2_rn(x, y);
    return *reinterpret_cast<uint32_t*>(&h);
}

__device__ __forceinline__ void mma_f16(float* c, const uint32_t* a, const uint32_t* b) {
    asm volatile(
        "mma.sync.aligned.m16n8k16.row.col.f32.f16.f16.f32 "
        "{%0,%1,%2,%3}, {%4,%5,%6,%7}, {%8,%9}, {%0,%1,%2,%3};"
        : "+f"(c[0]), "+f"(c[1]), "+f"(c[2]), "+f"(c[3])
        : "r"(a[0]), "r"(a[1]), "r"(a[2]), "r"(a[3]), "r"(b[0]), "r"(b[1]));
}

__device__ __forceinline__ void ldmx4(uint32_t* r, const void* p) {
    uint32_t a = (uint32_t)__cvta_generic_to_shared(p);
    asm volatile("ldmatrix.sync.aligned.m8n8.x4.shared.b16 {%0,%1,%2,%3}, [%4];"
                 : "=r"(r[0]), "=r"(r[1]), "=r"(r[2]), "=r"(r[3]) : "r"(a));
}

__device__ __forceinline__ void ldmx2t(uint32_t& r0, uint32_t& r1, const void* p) {
    uint32_t a = (uint32_t)__cvta_generic_to_shared(p);
    asm volatile("ldmatrix.sync.aligned.m8n8.x2.trans.shared.b16 {%0,%1}, [%2];"
                 : "=r"(r0), "=r"(r1) : "r"(a));
}

__device__ __forceinline__ void cp16(void* sdst, const void* gsrc) {
    unsigned sa = (unsigned)__cvta_generic_to_shared(sdst);
    asm volatile("cp.async.cg.shared.global [%0], [%1], 16;" :: "r"(sa), "l"(gsrc));
}
#define CP_COMMIT() asm volatile("cp.async.commit_group;")
#define CP_WAIT0()  asm volatile("cp.async.wait_group 0;")
#define CP_WAIT1()  asm volatile("cp.async.wait_group 1;")

// ---------------------------------------------------------------------------
// Weight prep (single fp16 outputs)
// ---------------------------------------------------------------------------
__global__ void prep_wqkv_tiled(const float* __restrict__ Wq,
                                const float* __restrict__ Wk,
                                const float* __restrict__ Wv,
                                __half* __restrict__ o)
{
    __shared__ float t[32][33];
    int s = blockIdx.z >> 4, h = blockIdx.z & 15;
    const float* W = (s == 0) ? Wq : (s == 1) ? Wk : Wv;
    const float* in = W + (long)h * Dq * HDq;
    int d0 = blockIdx.y * 32, hd0 = blockIdx.x * 32;
    int tx = threadIdx.x, ty = threadIdx.y;
    #pragma unroll
    for (int i = 0; i < 32; i += 8)
        t[ty + i][tx] = in[(long)(d0 + ty + i) * HDq + hd0 + tx];
    __syncthreads();
    long nrow = (long)s * Dq + h * HDq + hd0;
    #pragma unroll
    for (int i = 0; i < 32; i += 8)
        o[(nrow + ty + i) * Dq + d0 + tx] = __float2half(t[tx][ty + i]);
}

// in: [K][N] fp32 -> out: [N][K] fp16
__global__ void transpose_f16(const float* __restrict__ in,
                              __half* __restrict__ o,
                              int K, int N)
{
    __shared__ float t[32][33];
    int k0 = blockIdx.y * 32, n0 = blockIdx.x * 32;
    int tx = threadIdx.x, ty = threadIdx.y;
    #pragma unroll
    for (int i = 0; i < 32; i += 8)
        t[ty + i][tx] = in[(long)(k0 + ty + i) * N + n0 + tx];
    __syncthreads();
    #pragma unroll
    for (int i = 0; i < 32; i += 8)
        o[(long)(n0 + ty + i) * K + k0 + tx] = __float2half(t[tx][ty + i]);
}

// ---------------------------------------------------------------------------
// LayerNorm -> fp16
// ---------------------------------------------------------------------------
__global__ void ln_f16(const float* __restrict__ x,
                       const float* __restrict__ g,
                       const float* __restrict__ b,
                       __half* __restrict__ o)
{
    __shared__ float red[16];
    int row = blockIdx.x;
    int t = threadIdx.x;
    const float4* xr = (const float4*)(x + (long)row * Dq);
    float4 v = xr[t];
    float s  = v.x + v.y + v.z + v.w;
    float ss = v.x * v.x + v.y * v.y + v.z * v.z + v.w * v.w;
    #pragma unroll
    for (int o2 = 16; o2 >= 1; o2 >>= 1) {
        s  += __shfl_xor_sync(0xffffffffu, s,  o2);
        ss += __shfl_xor_sync(0xffffffffu, ss, o2);
    }
    if ((t & 31) == 0) { red[t >> 5] = s; red[8 + (t >> 5)] = ss; }
    __syncthreads();
    float stot = 0.f, sstot = 0.f;
    #pragma unroll
    for (int w = 0; w < 8; w++) { stot += red[w]; sstot += red[8 + w]; }
    float mu  = stot * (1.f / Dq);
    float var = sstot * (1.f / Dq) - mu * mu;
    float inv = rsqrtf(var + LN_EPS);
    float4 gg = ((const float4*)g)[t];
    float4 bb = ((const float4*)b)[t];
    __half2 p0 = __floats2half2_rn((v.x - mu) * inv * gg.x + bb.x,
                                   (v.y - mu) * inv * gg.y + bb.y);
    __half2 p1 = __floats2half2_rn((v.z - mu) * inv * gg.z + bb.z,
                                   (v.w - mu) * inv * gg.w + bb.w);
    long base = (long)row * Dq + t * 4;
    *(__half2*)(o + base)     = p0;
    *(__half2*)(o + base + 2) = p1;
}

// ---------------------------------------------------------------------------
// Plain fp16 GEMM: C = A @ B.  A fp16 [M][K], B fp16 [N][K] (transposed).
// Tile 128x256, BK=64, 8 warps (2x4), warp 64x64, 3-stage cp.async,
// ldmatrix.x4 fragments, 1 barrier per 64-K step.
// EPI: 2 +bias+residual fp32; 3 +bias+relu -> fp16; 4 -> fp16 w/ q prescale
// ---------------------------------------------------------------------------
#define KPAD 72
#define AST (128 * KPAD)
#define BST (256 * KPAD)
#define STAGE (AST + BST)           // 27648 halves
#define GEMM_SMEM (3 * STAGE * 2)   // 165888 B

template <int EPI>
__global__ void __launch_bounds__(256, 1)
gemm_f16(const __half* __restrict__ A,
         const __half* __restrict__ B,
         const float* __restrict__ bias,
         const float* __restrict__ res,
         float* __restrict__ C,
         __half* __restrict__ Ch,
         int N, int K)
{
    extern __shared__ __half smem[];
    const int tid  = threadIdx.x;
    const int lane = tid & 31;
    const int warp = tid >> 5;
    const int wm = warp >> 2;
    const int wn = warp & 3;
    const int a_r = lane & 15;
    const int a_c = (lane >> 4) << 3;
    const int b_r = (lane & 7) + ((lane >> 4) << 3);
    const int b_c = ((lane >> 3) & 1) << 3;

    const int bm = blockIdx.y, bn = blockIdx.x;
    const __half* A_b = A + (long)bm * 128 * K;
    const __half* B_b = B + (long)bn * 256 * K;

    auto sA = [&](int st) -> __half* { return smem + st * STAGE; };
    auto sB = [&](int st) -> __half* { return smem + st * STAGE + AST; };

    auto ld_stage = [&](int st, int kt) {
        long k0 = (long)kt * 64;
        #pragma unroll
        for (int i = 0; i < 4; i++) {                    // A: 128 rows x 8 chunks
            int c = tid + i * 256;
            int row = c >> 3, ch = (c & 7) * 8;
            cp16(sA(st) + row * KPAD + ch, A_b + (long)row * K + k0 + ch);
        }
        #pragma unroll
        for (int i = 0; i < 8; i++) {                    // B: 256 rows x 8 chunks
            int c = tid + i * 256;
            int row = c >> 3, ch = (c & 7) * 8;
            cp16(sB(st) + row * KPAD + ch, B_b + (long)row * K + k0 + ch);
        }
    };

    float acc[4][8][4];
    #pragma unroll
    for (int i = 0; i < 4; i++)
        #pragma unroll
        for (int j = 0; j < 8; j++)
            #pragma unroll
            for (int r = 0; r < 4; r++) acc[i][j][r] = 0.f;

    const int KT = K / 64;
    ld_stage(0, 0); CP_COMMIT();
    ld_stage(1, 1); CP_COMMIT();

    int st = 0;
    for (int kt = 0; kt < KT; kt++) {
        if (kt + 1 < KT) { CP_WAIT1(); } else { CP_WAIT0(); }
        __syncthreads();
        if (kt + 2 < KT) {
            int wst = st + 2; if (wst >= 3) wst -= 3;
            ld_stage(wst, kt + 2);
            CP_COMMIT();
        }

        const __half* pA = sA(st);
        const __half* pB = sB(st);

        #pragma unroll
        for (int ks = 0; ks < 4; ks++) {
            const int k16 = ks * 16;
            uint32_t af[4][4], bf[8][2];
            #pragma unroll
            for (int mt = 0; mt < 4; mt++)
                ldmx4(af[mt], pA + (wm * 64 + mt * 16 + a_r) * KPAD + k16 + a_c);
            #pragma unroll
            for (int np = 0; np < 4; np++) {
                int row = wn * 64 + np * 16 + b_r;
                uint32_t r[4];
                ldmx4(r, pB + row * KPAD + k16 + b_c);
                bf[2*np][0] = r[0]; bf[2*np][1] = r[1];
                bf[2*np+1][0] = r[2]; bf[2*np+1][1] = r[3];
            }
            #pragma unroll
            for (int mt = 0; mt < 4; mt++)
                #pragma unroll
                for (int nt = 0; nt < 8; nt++)
                    mma_f16(acc[mt][nt], af[mt], bf[nt]);
        }
        if (++st == 3) st = 0;
    }

    // epilogue
    const int lr4 = lane >> 2;
    const int lc2 = (lane & 3) * 2;
    #pragma unroll
    for (int mt = 0; mt < 4; mt++) {
        #pragma unroll
        for (int nt = 0; nt < 8; nt++) {
            int c = bn * 256 + wn * 64 + nt * 8 + lc2;
            #pragma unroll
            for (int half = 0; half < 2; half++) {
                int r = bm * 128 + wm * 64 + mt * 16 + lr4 + half * 8;
                float v0 = acc[mt][nt][half * 2 + 0];
                float v1 = acc[mt][nt][half * 2 + 1];
                long off = (long)r * N + c;
                if (EPI == 2) {
                    float2 bv = *(const float2*)(bias + c);
                    float2 rv = *(const float2*)(res + off);
                    *(float2*)(C + off) = make_float2(v0 + bv.x + rv.x,
                                                      v1 + bv.y + rv.y);
                } else if (EPI == 3) {
                    float2 bv = *(const float2*)(bias + c);
                    v0 = fmaxf(v0 + bv.x, 0.f);
                    v1 = fmaxf(v1 + bv.y, 0.f);
                    *(__half2*)(Ch + off) = __floats2half2_rn(v0, v1);
                } else {  // EPI == 4: fp16, q cols prescaled
                    float scale = (c < Dq) ? ATT_SCALE : 1.f;
                    *(__half2*)(Ch + off) = __floats2half2_rn(v0 * scale, v1 * scale);
                }
            }
        }
    }
}

// ---------------------------------------------------------------------------
// Flash attention, plain fp16, KV tile 128 (halved softmax/barrier fixed cost).
// Block: 128 Q rows x (b,h); 8 warps x 16 rows; KV tile 128, double buffered.
// ---------------------------------------------------------------------------
#define FPAD 72
#define FLASH_SMEM ((128 * FPAD + 2 * 2 * 128 * FPAD) * 2)   // 92160 B

__global__ void __launch_bounds__(256)
flash_tc(const __half* __restrict__ qkv,
         __half* __restrict__ outp)
{
    extern __shared__ __half sm[];
    __half* QH = sm;

    const int qi  = gridDim.x - 1 - blockIdx.x;
    const int bh  = blockIdx.y;
    const int b   = bh >> 4;
    const int h   = bh & 15;
    const int tid  = threadIdx.x;
    const int lane = tid & 31;
    const int warp = tid >> 5;
    const int g  = lane >> 2;
    const int t2 = (lane & 3) * 2;
    const int a_r = lane & 15;
    const int a_c = (lane >> 4) << 3;
    const int b_r = (lane & 7) + ((lane >> 4) << 3);
    const int b_c = ((lane >> 3) & 1) << 3;

    const long rb = (long)b * Tq;
    const __half* qp = qkv + (rb + qi * 128) * (3 * Dq) + h * HDq;
    const __half* kp = qkv + rb * (3 * Dq) + Dq + h * HDq;
    const __half* vp = qkv + rb * (3 * Dq) + 2 * Dq + h * HDq;

    auto kvbase = [&](int st) -> __half* {
        return sm + 128 * FPAD + st * (2 * 128 * FPAD);
    };
    // 128 rows x 64 cols (8 chunks of 8) per matrix: 1024 chunks, 4 iters x 256 thr
    auto ldkv = [&](int st, int jt) {
        __half* KB = kvbase(st);
        #pragma unroll
        for (int i = 0; i < 4; i++) {
            int c = tid + i * 256;
            int row = c >> 3;              // 0..127
            int c8 = (c & 7) * 8;          // 0..56
            long go = (long)(jt * 128 + row) * (3 * Dq) + c8;
            int so = row * FPAD + c8;
            cp16(KB + so,              kp + go);
            cp16(KB + 128 * FPAD + so, vp + go);
        }
    };

    #pragma unroll
    for (int i = 0; i < 4; i++) {
        int c = tid + i * 256;
        int row = c >> 3;
        int c8 = (c & 7) * 8;
        cp16(QH + row * FPAD + c8, qp + (long)row * (3 * Dq) + c8);
    }
    ldkv(0, 0);
    CP_COMMIT();

    float oacc[8][4];
    #pragma unroll
    for (int nt = 0; nt < 8; nt++)
        #pragma unroll
        for (int e = 0; e < 4; e++) oacc[nt][e] = 0.f;
    float m0 = -1e30f, m1 = -1e30f, l0 = 0.f, l1 = 0.f;

    uint32_t qf[4][4];
    const int qrow0 = qi * 128 + warp * 16 + g;

    for (int jt = 0; jt <= qi; jt++) {
        CP_WAIT0();
        __syncthreads();
        if (jt < qi) { ldkv((jt + 1) & 1, jt + 1); CP_COMMIT(); }

        if (jt == 0) {
            #pragma unroll
            for (int kt = 0; kt < 4; kt++)
                ldmx4(qf[kt], QH + (warp * 16 + a_r) * FPAD + kt * 16 + a_c);
        }

        __half* KB = kvbase(jt & 1);
        const __half* KHs = KB;
        const __half* VHs = KB + 128 * FPAD;

        // ---- S = Q K^T over 128 keys (16 n-tiles) ----
        float sacc[16][4];
        #pragma unroll
        for (int nt = 0; nt < 16; nt++)
            #pragma unroll
            for (int e = 0; e < 4; e++) sacc[nt][e] = 0.f;

        #pragma unroll
        for (int kt = 0; kt < 4; kt++) {
            #pragma unroll
            for (int np = 0; np < 8; np++) {
                int row = np * 16 + b_r;
                uint32_t r[4];
                ldmx4(r, KHs + row * FPAD + kt * 16 + b_c);
                uint32_t f0[2] = { r[0], r[1] };
                uint32_t f1[2] = { r[2], r[3] };
                mma_f16(sacc[2*np],     qf[kt], f0);
                mma_f16(sacc[2*np + 1], qf[kt], f1);
            }
        }

        // ---- causal mask (only on the diagonal tile) ----
        if (jt == qi) {
            #pragma unroll
            for (int nt = 0; nt < 16; nt++) {
                int key0 = jt * 128 + nt * 8 + t2;
                if (key0     > qrow0)     sacc[nt][0] = -1e30f;
                if (key0 + 1 > qrow0)     sacc[nt][1] = -1e30f;
                if (key0     > qrow0 + 8) sacc[nt][2] = -1e30f;
                if (key0 + 1 > qrow0 + 8) sacc[nt][3] = -1e30f;
            }
        }

        // ---- online softmax ----
        float mx0 = -1e30f, mx1 = -1e30f;
        #pragma unroll
        for (int nt = 0; nt < 16; nt++) {
            mx0 = fmaxf(mx0, fmaxf(sacc[nt][0], sacc[nt][1]));
            mx1 = fmaxf(mx1, fmaxf(sacc[nt][2], sacc[nt][3]));
        }
        mx0 = fmaxf(mx0, __shfl_xor_sync(0xffffffffu, mx0, 1));
        mx0 = fmaxf(mx0, __shfl_xor_sync(0xffffffffu, mx0, 2));
        mx1 = fmaxf(mx1, __shfl_xor_sync(0xffffffffu, mx1, 1));
        mx1 = fmaxf(mx1, __shfl_xor_sync(0xffffffffu, mx1, 2));
        float mn0 = fmaxf(m0, mx0), mn1 = fmaxf(m1, mx1);
        float a0 = __expf(m0 - mn0), a1 = __expf(m1 - mn1);
        m0 = mn0; m1 = mn1;
        float rs0 = 0.f, rs1 = 0.f;
        #pragma unroll
        for (int nt = 0; nt < 16; nt++) {
            sacc[nt][0] = __expf(sacc[nt][0] - mn0); rs0 += sacc[nt][0];
            sacc[nt][1] = __expf(sacc[nt][1] - mn0); rs0 += sacc[nt][1];
            sacc[nt][2] = __expf(sacc[nt][2] - mn1); rs1 += sacc[nt][2];
            sacc[nt][3] = __expf(sacc[nt][3] - mn1); rs1 += sacc[nt][3];
        }
        rs0 += __shfl_xor_sync(0xffffffffu, rs0, 1);
        rs0 += __shfl_xor_sync(0xffffffffu, rs0, 2);
        rs1 += __shfl_xor_sync(0xffffffffu, rs1, 1);
        rs1 += __shfl_xor_sync(0xffffffffu, rs1, 2);
        l0 = l0 * a0 + rs0;
        l1 = l1 * a1 + rs1;
        #pragma unroll
        for (int nt = 0; nt < 8; nt++) {
            oacc[nt][0] *= a0; oacc[nt][1] *= a0;
            oacc[nt][2] *= a1; oacc[nt][3] *= a1;
        }

        // ---- O += P V over 128 keys (8 k16 groups) ----
        #pragma unroll
        for (int j = 0; j < 8; j++) {
            uint32_t ph[4];
            ph[0] = packh2(sacc[2*j][0],   sacc[2*j][1]);
            ph[1] = packh2(sacc[2*j][2],   sacc[2*j][3]);
            ph[2] = packh2(sacc[2*j+1][0], sacc[2*j+1][1]);
            ph[3] = packh2(sacc[2*j+1][2], sacc[2*j+1][3]);
            #pragma unroll
            for (int nt = 0; nt < 8; nt++) {
                uint32_t vf[2];
                ldmx2t(vf[0], vf[1], VHs + (j * 16 + (lane & 15)) * FPAD + nt * 8);
                mma_f16(oacc[nt], ph, vf);
            }
        }
    }

    float inv0 = 1.f / l0, inv1 = 1.f / l1;
    long row0 = (long)b * Tq + qi * 128 + warp * 16 + g;
    #pragma unroll
    for (int nt = 0; nt < 8; nt++) {
        int col = h * HDq + nt * 8 + t2;
        *(__half2*)(outp + row0 * Dq + col) =
            __floats2half2_rn(oacc[nt][0] * inv0, oacc[nt][1] * inv0);
        *(__half2*)(outp + (row0 + 8) * Dq + col) =
            __floats2half2_rn(oacc[nt][2] * inv1, oacc[nt][3] * inv1);
    }
}

// ---------------------------------------------------------------------------
// Launch
// ---------------------------------------------------------------------------
extern "C" void kernel_launch(void* const* d_in, const int* in_sizes, int n_in,
                              void* d_out, int out_size)
{
    const float* x   = (const float*)d_in[0];
    const float* Wq  = (const float*)d_in[1];
    const float* Wk  = (const float*)d_in[2];
    const float* Wv  = (const float*)d_in[3];
    const float* Wp  = (const float*)d_in[4];
    const float* bp  = (const float*)d_in[5];
    const float* W1  = (const float*)d_in[6];
    const float* b1  = (const float*)d_in[7];
    const float* W2  = (const float*)d_in[8];
    const float* b2  = (const float*)d_in[9];
    const float* g1  = (const float*)d_in[10];
    const float* be1 = (const float*)d_in[11];
    const float* g2  = (const float*)d_in[12];
    const float* be2 = (const float*)d_in[13];
    float* out = (float*)d_out;

    __half *p_h, *p_wqkv, *p_wp, *p_w1, *p_w2, *p_attn, *p_ff, *p_qkv;
    float *p_x1;
    cudaGetSymbolAddress((void**)&p_h,    g_h);
    cudaGetSymbolAddress((void**)&p_wqkv, g_wqkv);
    cudaGetSymbolAddress((void**)&p_wp,   g_wp);
    cudaGetSymbolAddress((void**)&p_w1,   g_w1);
    cudaGetSymbolAddress((void**)&p_w2,   g_w2);
    cudaGetSymbolAddress((void**)&p_qkv,  g_qkv);
    cudaGetSymbolAddress((void**)&p_attn, g_attn);
    cudaGetSymbolAddress((void**)&p_x1,   g_x1);
    cudaGetSymbolAddress((void**)&p_ff,   g_ff);

    cudaFuncSetAttribute(gemm_f16<2>, cudaFuncAttributeMaxDynamicSharedMemorySize, GEMM_SMEM);
    cudaFuncSetAttribute(gemm_f16<3>, cudaFuncAttributeMaxDynamicSharedMemorySize, GEMM_SMEM);
    cudaFuncSetAttribute(gemm_f16<4>, cudaFuncAttributeMaxDynamicSharedMemorySize, GEMM_SMEM);
    cudaFuncSetAttribute(flash_tc,    cudaFuncAttributeMaxDynamicSharedMemorySize, FLASH_SMEM);

    // weight prep
    prep_wqkv_tiled<<<dim3(HDq / 32, Dq / 32, 48), dim3(32, 8)>>>(Wq, Wk, Wv, p_wqkv);
    transpose_f16<<<dim3(Dq / 32, Dq / 32),  dim3(32, 8)>>>(Wp, p_wp, Dq, Dq);
    transpose_f16<<<dim3(DFF / 32, Dq / 32), dim3(32, 8)>>>(W1, p_w1, Dq, DFF);
    transpose_f16<<<dim3(Dq / 32, DFF / 32), dim3(32, 8)>>>(W2, p_w2, DFF, Dq);

    // LN1 -> fp16
    ln_f16<<<Mq, 256>>>(x, g1, be1, p_h);
    // QKV projection -> fp16, q prescaled
    gemm_f16<4><<<dim3(3 * Dq / 256, Mq / 128), 256, GEMM_SMEM>>>(
        p_h, p_wqkv, nullptr, nullptr, nullptr, p_qkv, 3 * Dq, Dq);
    // flash attention -> fp16
    flash_tc<<<dim3(Tq / 128, Bq * Hq), 256, FLASH_SMEM>>>(p_qkv, p_attn);
    // output projection + bias + residual(x)
    gemm_f16<2><<<dim3(Dq / 256, Mq / 128), 256, GEMM_SMEM>>>(
        p_attn, p_wp, bp, x, p_x1, nullptr, Dq, Dq);
    // LN2 -> fp16
    ln_f16<<<Mq, 256>>>(p_x1, g2, be2, p_h);
    // FFN up + bias + relu -> fp16
    gemm_f16<3><<<dim3(DFF / 256, Mq / 128), 256, GEMM_SMEM>>>(
        p_h, p_w1, b1, nullptr, nullptr, p_ff, DFF, Dq);
    // FFN down + bias + residual(x1) -> d_out
    gemm_f16<2><<<dim3(Dq / 256, Mq / 128), 256, GEMM_SMEM>>>(
        p_ff, p_w2, b2, p_x1, out, nullptr, Dq, DFF);
}

// round 13
// speedup vs baseline: 3.2191x; 1.0099x over previous
#include <cuda_runtime.h>
#include <cuda_fp16.h>
#include <stdint.h>

// Problem constants
#define Bq   4
#define Tq   2048
#define Dq   1024
#define Hq   16
#define HDq  64
#define Mq   (Bq * Tq)        // 8192
#define DFF  (4 * Dq)         // 4096
#define LN_EPS 1e-5f
#define ATT_SCALE 0.125f

// ---------------------------------------------------------------------------
// Scratch
// ---------------------------------------------------------------------------
__device__ __half g_h[Mq * Dq];            // LN out fp16
__device__ __half g_wqkv[3*Dq*Dq];         // [3D][D] fp16
__device__ __half g_wp[Dq*Dq];             // [D][D] transposed fp16
__device__ __half g_w1[DFF*Dq];            // [4D][D] fp16
__device__ __half g_w2[Dq*DFF];            // [D][4D] fp16
__device__ __half g_qkv[Mq * 3 * Dq];      // q pre-scaled, fp16
__device__ __half g_attn[Mq * Dq];         // flash out fp16
__device__ float  g_x1[Mq * Dq];
__device__ __half g_ff[Mq * DFF];          // FFN hidden fp16

// ---------------------------------------------------------------------------
// Helpers
// ---------------------------------------------------------------------------
__device__ __forceinline__ uint32_t packh2(float x, float y) {
    __half2 h = __floats2half2_rn(x, y);
    return *reinterpret_cast<uint32_t*>(&h);
}

__device__ __forceinline__ void mma_f16(float* c, const uint32_t* a, const uint32_t* b) {
    asm volatile(
        "mma.sync.aligned.m16n8k16.row.col.f32.f16.f16.f32 "
        "{%0,%1,%2,%3}, {%4,%5,%6,%7}, {%8,%9}, {%0,%1,%2,%3};"
        : "+f"(c[0]), "+f"(c[1]), "+f"(c[2]), "+f"(c[3])
        : "r"(a[0]), "r"(a[1]), "r"(a[2]), "r"(a[3]), "r"(b[0]), "r"(b[1]));
}

__device__ __forceinline__ void ldmx4(uint32_t* r, const void* p) {
    uint32_t a = (uint32_t)__cvta_generic_to_shared(p);
    asm volatile("ldmatrix.sync.aligned.m8n8.x4.shared.b16 {%0,%1,%2,%3}, [%4];"
                 : "=r"(r[0]), "=r"(r[1]), "=r"(r[2]), "=r"(r[3]) : "r"(a));
}

__device__ __forceinline__ void ldmx2t(uint32_t& r0, uint32_t& r1, const void* p) {
    uint32_t a = (uint32_t)__cvta_generic_to_shared(p);
    asm volatile("ldmatrix.sync.aligned.m8n8.x2.trans.shared.b16 {%0,%1}, [%2];"
                 : "=r"(r0), "=r"(r1) : "r"(a));
}

__device__ __forceinline__ void cp16(void* sdst, const void* gsrc) {
    unsigned sa = (unsigned)__cvta_generic_to_shared(sdst);
    asm volatile("cp.async.cg.shared.global [%0], [%1], 16;" :: "r"(sa), "l"(gsrc));
}
#define CP_COMMIT() asm volatile("cp.async.commit_group;")
#define CP_WAIT0()  asm volatile("cp.async.wait_group 0;")
#define CP_WAIT1()  asm volatile("cp.async.wait_group 1;")

// ---------------------------------------------------------------------------
// Merged weight prep: ALL four weight transposes in ONE launch (12288 blocks).
//   blocks [0, 3072)        : Wq/Wk/Wv -> g_wqkv  [3D][D]
//   blocks [3072, 4096)     : Wp  -> g_wp  [D][D]
//   blocks [4096, 8192)     : W1  -> g_w1  [4D][D]
//   blocks [8192, 12288)    : W2  -> g_w2  [D][4D]
// Each block transposes one 32x32 tile (32x8 threads).
// ---------------------------------------------------------------------------
__global__ void prep_all(const float* __restrict__ Wq,
                         const float* __restrict__ Wk,
                         const float* __restrict__ Wv,
                         const float* __restrict__ Wp,
                         const float* __restrict__ W1,
                         const float* __restrict__ W2,
                         __half* __restrict__ o_qkv,
                         __half* __restrict__ o_p,
                         __half* __restrict__ o_1,
                         __half* __restrict__ o_2)
{
    __shared__ float t[32][33];
    int bid = blockIdx.x;
    int tx = threadIdx.x, ty = threadIdx.y;

    if (bid < 3072) {
        // wqkv: 48 (s,h) slices x 64 tiles (32 d-tiles x 2 hd-tiles)
        int sh = bid >> 6;              // 0..47
        int tI = bid & 63;
        int s = sh >> 4, h = sh & 15;
        const float* W = (s == 0) ? Wq : (s == 1) ? Wk : Wv;
        const float* in = W + (long)h * Dq * HDq;   // [Dq][64]
        int d0  = (tI >> 1) * 32;
        int hd0 = (tI & 1) * 32;
        #pragma unroll
        for (int i = 0; i < 32; i += 8)
            t[ty + i][tx] = in[(long)(d0 + ty + i) * HDq + hd0 + tx];
        __syncthreads();
        long nrow = (long)s * Dq + h * HDq + hd0;
        #pragma unroll
        for (int i = 0; i < 32; i += 8)
            o_qkv[(nrow + ty + i) * Dq + d0 + tx] = __float2half(t[tx][ty + i]);
        return;
    }

    const float* in; __half* out; int K, N;
    bid -= 3072;
    if (bid < 1024)      { in = Wp; out = o_p; K = Dq;  N = Dq;  }
    else if (bid < 5120) { bid -= 1024; in = W1; out = o_1; K = Dq;  N = DFF; }
    else                 { bid -= 5120; in = W2; out = o_2; K = DFF; N = Dq;  }

    int ntn = N >> 5;
    int k0 = (bid / ntn) * 32;
    int n0 = (bid % ntn) * 32;
    #pragma unroll
    for (int i = 0; i < 32; i += 8)
        t[ty + i][tx] = in[(long)(k0 + ty + i) * N + n0 + tx];
    __syncthreads();
    #pragma unroll
    for (int i = 0; i < 32; i += 8)
        out[(long)(n0 + ty + i) * K + k0 + tx] = __float2half(t[tx][ty + i]);
}

// ---------------------------------------------------------------------------
// LayerNorm -> fp16
// ---------------------------------------------------------------------------
__global__ void ln_f16(const float* __restrict__ x,
                       const float* __restrict__ g,
                       const float* __restrict__ b,
                       __half* __restrict__ o)
{
    __shared__ float red[16];
    int row = blockIdx.x;
    int t = threadIdx.x;
    const float4* xr = (const float4*)(x + (long)row * Dq);
    float4 v = xr[t];
    float s  = v.x + v.y + v.z + v.w;
    float ss = v.x * v.x + v.y * v.y + v.z * v.z + v.w * v.w;
    #pragma unroll
    for (int o2 = 16; o2 >= 1; o2 >>= 1) {
        s  += __shfl_xor_sync(0xffffffffu, s,  o2);
        ss += __shfl_xor_sync(0xffffffffu, ss, o2);
    }
    if ((t & 31) == 0) { red[t >> 5] = s; red[8 + (t >> 5)] = ss; }
    __syncthreads();
    float stot = 0.f, sstot = 0.f;
    #pragma unroll
    for (int w = 0; w < 8; w++) { stot += red[w]; sstot += red[8 + w]; }
    float mu  = stot * (1.f / Dq);
    float var = sstot * (1.f / Dq) - mu * mu;
    float inv = rsqrtf(var + LN_EPS);
    float4 gg = ((const float4*)g)[t];
    float4 bb = ((const float4*)b)[t];
    __half2 p0 = __floats2half2_rn((v.x - mu) * inv * gg.x + bb.x,
                                   (v.y - mu) * inv * gg.y + bb.y);
    __half2 p1 = __floats2half2_rn((v.z - mu) * inv * gg.z + bb.z,
                                   (v.w - mu) * inv * gg.w + bb.w);
    long base = (long)row * Dq + t * 4;
    *(__half2*)(o + base)     = p0;
    *(__half2*)(o + base + 2) = p1;
}

// ---------------------------------------------------------------------------
// Plain fp16 GEMM: C = A @ B.  A fp16 [M][K], B fp16 [N][K] (transposed).
// Tile 128x256, BK=64, 8 warps (2x4), warp 64x64, 3-stage cp.async,
// ldmatrix.x4 fragments, 1 barrier per 64-K step.
// EPI: 2 +bias+residual fp32; 3 +bias+relu -> fp16; 4 -> fp16 w/ q prescale
// ---------------------------------------------------------------------------
#define KPAD 72
#define AST (128 * KPAD)
#define BST (256 * KPAD)
#define STAGE (AST + BST)           // 27648 halves
#define GEMM_SMEM (3 * STAGE * 2)   // 165888 B

template <int EPI>
__global__ void __launch_bounds__(256, 1)
gemm_f16(const __half* __restrict__ A,
         const __half* __restrict__ B,
         const float* __restrict__ bias,
         const float* __restrict__ res,
         float* __restrict__ C,
         __half* __restrict__ Ch,
         int N, int K)
{
    extern __shared__ __half smem[];
    const int tid  = threadIdx.x;
    const int lane = tid & 31;
    const int warp = tid >> 5;
    const int wm = warp >> 2;
    const int wn = warp & 3;
    const int a_r = lane & 15;
    const int a_c = (lane >> 4) << 3;
    const int b_r = (lane & 7) + ((lane >> 4) << 3);
    const int b_c = ((lane >> 3) & 1) << 3;

    const int bm = blockIdx.y, bn = blockIdx.x;
    const __half* A_b = A + (long)bm * 128 * K;
    const __half* B_b = B + (long)bn * 256 * K;

    auto sA = [&](int st) -> __half* { return smem + st * STAGE; };
    auto sB = [&](int st) -> __half* { return smem + st * STAGE + AST; };

    auto ld_stage = [&](int st, int kt) {
        long k0 = (long)kt * 64;
        #pragma unroll
        for (int i = 0; i < 4; i++) {
            int c = tid + i * 256;
            int row = c >> 3, ch = (c & 7) * 8;
            cp16(sA(st) + row * KPAD + ch, A_b + (long)row * K + k0 + ch);
        }
        #pragma unroll
        for (int i = 0; i < 8; i++) {
            int c = tid + i * 256;
            int row = c >> 3, ch = (c & 7) * 8;
            cp16(sB(st) + row * KPAD + ch, B_b + (long)row * K + k0 + ch);
        }
    };

    float acc[4][8][4];
    #pragma unroll
    for (int i = 0; i < 4; i++)
        #pragma unroll
        for (int j = 0; j < 8; j++)
            #pragma unroll
            for (int r = 0; r < 4; r++) acc[i][j][r] = 0.f;

    const int KT = K / 64;
    ld_stage(0, 0); CP_COMMIT();
    ld_stage(1, 1); CP_COMMIT();

    int st = 0;
    for (int kt = 0; kt < KT; kt++) {
        if (kt + 1 < KT) { CP_WAIT1(); } else { CP_WAIT0(); }
        __syncthreads();
        if (kt + 2 < KT) {
            int wst = st + 2; if (wst >= 3) wst -= 3;
            ld_stage(wst, kt + 2);
            CP_COMMIT();
        }

        const __half* pA = sA(st);
        const __half* pB = sB(st);

        #pragma unroll
        for (int ks = 0; ks < 4; ks++) {
            const int k16 = ks * 16;
            uint32_t af[4][4], bf[8][2];
            #pragma unroll
            for (int mt = 0; mt < 4; mt++)
                ldmx4(af[mt], pA + (wm * 64 + mt * 16 + a_r) * KPAD + k16 + a_c);
            #pragma unroll
            for (int np = 0; np < 4; np++) {
                int row = wn * 64 + np * 16 + b_r;
                uint32_t r[4];
                ldmx4(r, pB + row * KPAD + k16 + b_c);
                bf[2*np][0] = r[0]; bf[2*np][1] = r[1];
                bf[2*np+1][0] = r[2]; bf[2*np+1][1] = r[3];
            }
            #pragma unroll
            for (int mt = 0; mt < 4; mt++)
                #pragma unroll
                for (int nt = 0; nt < 8; nt++)
                    mma_f16(acc[mt][nt], af[mt], bf[nt]);
        }
        if (++st == 3) st = 0;
    }

    // epilogue
    const int lr4 = lane >> 2;
    const int lc2 = (lane & 3) * 2;
    #pragma unroll
    for (int mt = 0; mt < 4; mt++) {
        #pragma unroll
        for (int nt = 0; nt < 8; nt++) {
            int c = bn * 256 + wn * 64 + nt * 8 + lc2;
            #pragma unroll
            for (int half = 0; half < 2; half++) {
                int r = bm * 128 + wm * 64 + mt * 16 + lr4 + half * 8;
                float v0 = acc[mt][nt][half * 2 + 0];
                float v1 = acc[mt][nt][half * 2 + 1];
                long off = (long)r * N + c;
                if (EPI == 2) {
                    float2 bv = *(const float2*)(bias + c);
                    float2 rv = *(const float2*)(res + off);
                    *(float2*)(C + off) = make_float2(v0 + bv.x + rv.x,
                                                      v1 + bv.y + rv.y);
                } else if (EPI == 3) {
                    float2 bv = *(const float2*)(bias + c);
                    v0 = fmaxf(v0 + bv.x, 0.f);
                    v1 = fmaxf(v1 + bv.y, 0.f);
                    *(__half2*)(Ch + off) = __floats2half2_rn(v0, v1);
                } else {  // EPI == 4: fp16, q cols prescaled
                    float scale = (c < Dq) ? ATT_SCALE : 1.f;
                    *(__half2*)(Ch + off) = __floats2half2_rn(v0 * scale, v1 * scale);
                }
            }
        }
    }
}

// ---------------------------------------------------------------------------
// Flash attention, plain fp16, KV tile 128.
// ---------------------------------------------------------------------------
#define FPAD 72
#define FLASH_SMEM ((128 * FPAD + 2 * 2 * 128 * FPAD) * 2)   // 92160 B

__global__ void __launch_bounds__(256)
flash_tc(const __half* __restrict__ qkv,
         __half* __restrict__ outp)
{
    extern __shared__ __half sm[];
    __half* QH = sm;

    const int qi  = gridDim.x - 1 - blockIdx.x;
    const int bh  = blockIdx.y;
    const int b   = bh >> 4;
    const int h   = bh & 15;
    const int tid  = threadIdx.x;
    const int lane = tid & 31;
    const int warp = tid >> 5;
    const int g  = lane >> 2;
    const int t2 = (lane & 3) * 2;
    const int a_r = lane & 15;
    const int a_c = (lane >> 4) << 3;
    const int b_r = (lane & 7) + ((lane >> 4) << 3);
    const int b_c = ((lane >> 3) & 1) << 3;

    const long rb = (long)b * Tq;
    const __half* qp = qkv + (rb + qi * 128) * (3 * Dq) + h * HDq;
    const __half* kp = qkv + rb * (3 * Dq) + Dq + h * HDq;
    const __half* vp = qkv + rb * (3 * Dq) + 2 * Dq + h * HDq;

    auto kvbase = [&](int st) -> __half* {
        return sm + 128 * FPAD + st * (2 * 128 * FPAD);
    };
    auto ldkv = [&](int st, int jt) {
        __half* KB = kvbase(st);
        #pragma unroll
        for (int i = 0; i < 4; i++) {
            int c = tid + i * 256;
            int row = c >> 3;
            int c8 = (c & 7) * 8;
            long go = (long)(jt * 128 + row) * (3 * Dq) + c8;
            int so = row * FPAD + c8;
            cp16(KB + so,              kp + go);
            cp16(KB + 128 * FPAD + so, vp + go);
        }
    };

    #pragma unroll
    for (int i = 0; i < 4; i++) {
        int c = tid + i * 256;
        int row = c >> 3;
        int c8 = (c & 7) * 8;
        cp16(QH + row * FPAD + c8, qp + (long)row * (3 * Dq) + c8);
    }
    ldkv(0, 0);
    CP_COMMIT();

    float oacc[8][4];
    #pragma unroll
    for (int nt = 0; nt < 8; nt++)
        #pragma unroll
        for (int e = 0; e < 4; e++) oacc[nt][e] = 0.f;
    float m0 = -1e30f, m1 = -1e30f, l0 = 0.f, l1 = 0.f;

    uint32_t qf[4][4];
    const int qrow0 = qi * 128 + warp * 16 + g;

    for (int jt = 0; jt <= qi; jt++) {
        CP_WAIT0();
        __syncthreads();
        if (jt < qi) { ldkv((jt + 1) & 1, jt + 1); CP_COMMIT(); }

        if (jt == 0) {
            #pragma unroll
            for (int kt = 0; kt < 4; kt++)
                ldmx4(qf[kt], QH + (warp * 16 + a_r) * FPAD + kt * 16 + a_c);
        }

        __half* KB = kvbase(jt & 1);
        const __half* KHs = KB;
        const __half* VHs = KB + 128 * FPAD;

        float sacc[16][4];
        #pragma unroll
        for (int nt = 0; nt < 16; nt++)
            #pragma unroll
            for (int e = 0; e < 4; e++) sacc[nt][e] = 0.f;

        #pragma unroll
        for (int kt = 0; kt < 4; kt++) {
            #pragma unroll
            for (int np = 0; np < 8; np++) {
                int row = np * 16 + b_r;
                uint32_t r[4];
                ldmx4(r, KHs + row * FPAD + kt * 16 + b_c);
                uint32_t f0[2] = { r[0], r[1] };
                uint32_t f1[2] = { r[2], r[3] };
                mma_f16(sacc[2*np],     qf[kt], f0);
                mma_f16(sacc[2*np + 1], qf[kt], f1);
            }
        }

        if (jt == qi) {
            #pragma unroll
            for (int nt = 0; nt < 16; nt++) {
                int key0 = jt * 128 + nt * 8 + t2;
                if (key0     > qrow0)     sacc[nt][0] = -1e30f;
                if (key0 + 1 > qrow0)     sacc[nt][1] = -1e30f;
                if (key0     > qrow0 + 8) sacc[nt][2] = -1e30f;
                if (key0 + 1 > qrow0 + 8) sacc[nt][3] = -1e30f;
            }
        }

        float mx0 = -1e30f, mx1 = -1e30f;
        #pragma unroll
        for (int nt = 0; nt < 16; nt++) {
            mx0 = fmaxf(mx0, fmaxf(sacc[nt][0], sacc[nt][1]));
            mx1 = fmaxf(mx1, fmaxf(sacc[nt][2], sacc[nt][3]));
        }
        mx0 = fmaxf(mx0, __shfl_xor_sync(0xffffffffu, mx0, 1));
        mx0 = fmaxf(mx0, __shfl_xor_sync(0xffffffffu, mx0, 2));
        mx1 = fmaxf(mx1, __shfl_xor_sync(0xffffffffu, mx1, 1));
        mx1 = fmaxf(mx1, __shfl_xor_sync(0xffffffffu, mx1, 2));
        float mn0 = fmaxf(m0, mx0), mn1 = fmaxf(m1, mx1);
        float a0 = __expf(m0 - mn0), a1 = __expf(m1 - mn1);
        m0 = mn0; m1 = mn1;
        float rs0 = 0.f, rs1 = 0.f;
        #pragma unroll
        for (int nt = 0; nt < 16; nt++) {
            sacc[nt][0] = __expf(sacc[nt][0] - mn0); rs0 += sacc[nt][0];
            sacc[nt][1] = __expf(sacc[nt][1] - mn0); rs0 += sacc[nt][1];
            sacc[nt][2] = __expf(sacc[nt][2] - mn1); rs1 += sacc[nt][2];
            sacc[nt][3] = __expf(sacc[nt][3] - mn1); rs1 += sacc[nt][3];
        }
        rs0 += __shfl_xor_sync(0xffffffffu, rs0, 1);
        rs0 += __shfl_xor_sync(0xffffffffu, rs0, 2);
        rs1 += __shfl_xor_sync(0xffffffffu, rs1, 1);
        rs1 += __shfl_xor_sync(0xffffffffu, rs1, 2);
        l0 = l0 * a0 + rs0;
        l1 = l1 * a1 + rs1;
        #pragma unroll
        for (int nt = 0; nt < 8; nt++) {
            oacc[nt][0] *= a0; oacc[nt][1] *= a0;
            oacc[nt][2] *= a1; oacc[nt][3] *= a1;
        }

        #pragma unroll
        for (int j = 0; j < 8; j++) {
            uint32_t ph[4];
            ph[0] = packh2(sacc[2*j][0],   sacc[2*j][1]);
            ph[1] = packh2(sacc[2*j][2],   sacc[2*j][3]);
            ph[2] = packh2(sacc[2*j+1][0], sacc[2*j+1][1]);
            ph[3] = packh2(sacc[2*j+1][2], sacc[2*j+1][3]);
            #pragma unroll
            for (int nt = 0; nt < 8; nt++) {
                uint32_t vf[2];
                ldmx2t(vf[0], vf[1], VHs + (j * 16 + (lane & 15)) * FPAD + nt * 8);
                mma_f16(oacc[nt], ph, vf);
            }
        }
    }

    float inv0 = 1.f / l0, inv1 = 1.f / l1;
    long row0 = (long)b * Tq + qi * 128 + warp * 16 + g;
    #pragma unroll
    for (int nt = 0; nt < 8; nt++) {
        int col = h * HDq + nt * 8 + t2;
        *(__half2*)(outp + row0 * Dq + col) =
            __floats2half2_rn(oacc[nt][0] * inv0, oacc[nt][1] * inv0);
        *(__half2*)(outp + (row0 + 8) * Dq + col) =
            __floats2half2_rn(oacc[nt][2] * inv1, oacc[nt][3] * inv1);
    }
}

// ---------------------------------------------------------------------------
// Launch
// ---------------------------------------------------------------------------
extern "C" void kernel_launch(void* const* d_in, const int* in_sizes, int n_in,
                              void* d_out, int out_size)
{
    const float* x   = (const float*)d_in[0];
    const float* Wq  = (const float*)d_in[1];
    const float* Wk  = (const float*)d_in[2];
    const float* Wv  = (const float*)d_in[3];
    const float* Wp  = (const float*)d_in[4];
    const float* bp  = (const float*)d_in[5];
    const float* W1  = (const float*)d_in[6];
    const float* b1  = (const float*)d_in[7];
    const float* W2  = (const float*)d_in[8];
    const float* b2  = (const float*)d_in[9];
    const float* g1  = (const float*)d_in[10];
    const float* be1 = (const float*)d_in[11];
    const float* g2  = (const float*)d_in[12];
    const float* be2 = (const float*)d_in[13];
    float* out = (float*)d_out;

    __half *p_h, *p_wqkv, *p_wp, *p_w1, *p_w2, *p_attn, *p_ff, *p_qkv;
    float *p_x1;
    cudaGetSymbolAddress((void**)&p_h,    g_h);
    cudaGetSymbolAddress((void**)&p_wqkv, g_wqkv);
    cudaGetSymbolAddress((void**)&p_wp,   g_wp);
    cudaGetSymbolAddress((void**)&p_w1,   g_w1);
    cudaGetSymbolAddress((void**)&p_w2,   g_w2);
    cudaGetSymbolAddress((void**)&p_qkv,  g_qkv);
    cudaGetSymbolAddress((void**)&p_attn, g_attn);
    cudaGetSymbolAddress((void**)&p_x1,   g_x1);
    cudaGetSymbolAddress((void**)&p_ff,   g_ff);

    cudaFuncSetAttribute(gemm_f16<2>, cudaFuncAttributeMaxDynamicSharedMemorySize, GEMM_SMEM);
    cudaFuncSetAttribute(gemm_f16<3>, cudaFuncAttributeMaxDynamicSharedMemorySize, GEMM_SMEM);
    cudaFuncSetAttribute(gemm_f16<4>, cudaFuncAttributeMaxDynamicSharedMemorySize, GEMM_SMEM);
    cudaFuncSetAttribute(flash_tc,    cudaFuncAttributeMaxDynamicSharedMemorySize, FLASH_SMEM);

    // merged weight prep (single launch, 12288 tile-blocks)
    prep_all<<<12288, dim3(32, 8)>>>(Wq, Wk, Wv, Wp, W1, W2,
                                     p_wqkv, p_wp, p_w1, p_w2);

    // LN1 -> fp16
    ln_f16<<<Mq, 256>>>(x, g1, be1, p_h);
    // QKV projection -> fp16, q prescaled
    gemm_f16<4><<<dim3(3 * Dq / 256, Mq / 128), 256, GEMM_SMEM>>>(
        p_h, p_wqkv, nullptr, nullptr, nullptr, p_qkv, 3 * Dq, Dq);
    // flash attention -> fp16
    flash_tc<<<dim3(Tq / 128, Bq * Hq), 256, FLASH_SMEM>>>(p_qkv, p_attn);
    // output projection + bias + residual(x)
    gemm_f16<2><<<dim3(Dq / 256, Mq / 128), 256, GEMM_SMEM>>>(
        p_attn, p_wp, bp, x, p_x1, nullptr, Dq, Dq);
    // LN2 -> fp16
    ln_f16<<<Mq, 256>>>(p_x1, g2, be2, p_h);
    // FFN up + bias + relu -> fp16
    gemm_f16<3><<<dim3(DFF / 256, Mq / 128), 256, GEMM_SMEM>>>(
        p_h, p_w1, b1, nullptr, nullptr, p_ff, DFF, Dq);
    // FFN down + bias + residual(x1) -> d_out
    gemm_f16<2><<<dim3(Dq / 256, Mq / 128), 256, GEMM_SMEM>>>(
        p_ff, p_w2, b2, p_x1, out, nullptr, Dq, DFF);
}

// round 14
// speedup vs baseline: 3.5052x; 1.0889x over previous
#include <cuda_runtime.h>
#include <cuda_fp16.h>
#include <stdint.h>

// Problem constants
#define Bq   4
#define Tq   2048
#define Dq   1024
#define Hq   16
#define HDq  64
#define Mq   (Bq * Tq)        // 8192
#define DFF  (4 * Dq)         // 4096
#define LN_EPS 1e-5f
#define ATT_SCALE 0.125f

// ---------------------------------------------------------------------------
// Scratch
// ---------------------------------------------------------------------------
__device__ __half g_h[Mq * Dq];            // LN out fp16
__device__ __half g_wqkv[3*Dq*Dq];         // [3D][D] fp16
__device__ __half g_wp[Dq*Dq];             // [D][D] transposed fp16
__device__ __half g_w1[DFF*Dq];            // [4D][D] fp16
__device__ __half g_w2[Dq*DFF];            // [D][4D] fp16
__device__ __half g_qkv[Mq * 3 * Dq];      // q pre-scaled, fp16
__device__ __half g_attn[Mq * Dq];         // flash out fp16
__device__ float  g_x1[Mq * Dq];
__device__ __half g_ff[Mq * DFF];          // FFN hidden fp16

// ---------------------------------------------------------------------------
// Helpers
// ---------------------------------------------------------------------------
__device__ __forceinline__ uint32_t packh2(float x, float y) {
    __half2 h = __floats2half2_rn(x, y);
    return *reinterpret_cast<uint32_t*>(&h);
}

__device__ __forceinline__ void mma_f16(float* c, const uint32_t* a, const uint32_t* b) {
    asm volatile(
        "mma.sync.aligned.m16n8k16.row.col.f32.f16.f16.f32 "
        "{%0,%1,%2,%3}, {%4,%5,%6,%7}, {%8,%9}, {%0,%1,%2,%3};"
        : "+f"(c[0]), "+f"(c[1]), "+f"(c[2]), "+f"(c[3])
        : "r"(a[0]), "r"(a[1]), "r"(a[2]), "r"(a[3]), "r"(b[0]), "r"(b[1]));
}

__device__ __forceinline__ void ldmx4(uint32_t* r, const void* p) {
    uint32_t a = (uint32_t)__cvta_generic_to_shared(p);
    asm volatile("ldmatrix.sync.aligned.m8n8.x4.shared.b16 {%0,%1,%2,%3}, [%4];"
                 : "=r"(r[0]), "=r"(r[1]), "=r"(r[2]), "=r"(r[3]) : "r"(a));
}

__device__ __forceinline__ void ldmx2t(uint32_t& r0, uint32_t& r1, const void* p) {
    uint32_t a = (uint32_t)__cvta_generic_to_shared(p);
    asm volatile("ldmatrix.sync.aligned.m8n8.x2.trans.shared.b16 {%0,%1}, [%2];"
                 : "=r"(r0), "=r"(r1) : "r"(a));
}

__device__ __forceinline__ void cp16(void* sdst, const void* gsrc) {
    unsigned sa = (unsigned)__cvta_generic_to_shared(sdst);
    asm volatile("cp.async.cg.shared.global [%0], [%1], 16;" :: "r"(sa), "l"(gsrc));
}
#define CP_COMMIT() asm volatile("cp.async.commit_group;")
#define CP_WAIT0()  asm volatile("cp.async.wait_group 0;")

// ---------------------------------------------------------------------------
// Merged weight prep: ALL four weight transposes in ONE launch (12288 blocks).
// ---------------------------------------------------------------------------
__global__ void prep_all(const float* __restrict__ Wq,
                         const float* __restrict__ Wk,
                         const float* __restrict__ Wv,
                         const float* __restrict__ Wp,
                         const float* __restrict__ W1,
                         const float* __restrict__ W2,
                         __half* __restrict__ o_qkv,
                         __half* __restrict__ o_p,
                         __half* __restrict__ o_1,
                         __half* __restrict__ o_2)
{
    __shared__ float t[32][33];
    int bid = blockIdx.x;
    int tx = threadIdx.x, ty = threadIdx.y;

    if (bid < 3072) {
        int sh = bid >> 6;
        int tI = bid & 63;
        int s = sh >> 4, h = sh & 15;
        const float* W = (s == 0) ? Wq : (s == 1) ? Wk : Wv;
        const float* in = W + (long)h * Dq * HDq;
        int d0  = (tI >> 1) * 32;
        int hd0 = (tI & 1) * 32;
        #pragma unroll
        for (int i = 0; i < 32; i += 8)
            t[ty + i][tx] = in[(long)(d0 + ty + i) * HDq + hd0 + tx];
        __syncthreads();
        long nrow = (long)s * Dq + h * HDq + hd0;
        #pragma unroll
        for (int i = 0; i < 32; i += 8)
            o_qkv[(nrow + ty + i) * Dq + d0 + tx] = __float2half(t[tx][ty + i]);
        return;
    }

    const float* in; __half* out; int K, N;
    bid -= 3072;
    if (bid < 1024)      { in = Wp; out = o_p; K = Dq;  N = Dq;  }
    else if (bid < 5120) { bid -= 1024; in = W1; out = o_1; K = Dq;  N = DFF; }
    else                 { bid -= 5120; in = W2; out = o_2; K = DFF; N = Dq;  }

    int ntn = N >> 5;
    int k0 = (bid / ntn) * 32;
    int n0 = (bid % ntn) * 32;
    #pragma unroll
    for (int i = 0; i < 32; i += 8)
        t[ty + i][tx] = in[(long)(k0 + ty + i) * N + n0 + tx];
    __syncthreads();
    #pragma unroll
    for (int i = 0; i < 32; i += 8)
        out[(long)(n0 + ty + i) * K + k0 + tx] = __float2half(t[tx][ty + i]);
}

// ---------------------------------------------------------------------------
// LayerNorm -> fp16
// ---------------------------------------------------------------------------
__global__ void ln_f16(const float* __restrict__ x,
                       const float* __restrict__ g,
                       const float* __restrict__ b,
                       __half* __restrict__ o)
{
    __shared__ float red[16];
    int row = blockIdx.x;
    int t = threadIdx.x;
    const float4* xr = (const float4*)(x + (long)row * Dq);
    float4 v = xr[t];
    float s  = v.x + v.y + v.z + v.w;
    float ss = v.x * v.x + v.y * v.y + v.z * v.z + v.w * v.w;
    #pragma unroll
    for (int o2 = 16; o2 >= 1; o2 >>= 1) {
        s  += __shfl_xor_sync(0xffffffffu, s,  o2);
        ss += __shfl_xor_sync(0xffffffffu, ss, o2);
    }
    if ((t & 31) == 0) { red[t >> 5] = s; red[8 + (t >> 5)] = ss; }
    __syncthreads();
    float stot = 0.f, sstot = 0.f;
    #pragma unroll
    for (int w = 0; w < 8; w++) { stot += red[w]; sstot += red[8 + w]; }
    float mu  = stot * (1.f / Dq);
    float var = sstot * (1.f / Dq) - mu * mu;
    float inv = rsqrtf(var + LN_EPS);
    float4 gg = ((const float4*)g)[t];
    float4 bb = ((const float4*)b)[t];
    __half2 p0 = __floats2half2_rn((v.x - mu) * inv * gg.x + bb.x,
                                   (v.y - mu) * inv * gg.y + bb.y);
    __half2 p1 = __floats2half2_rn((v.z - mu) * inv * gg.z + bb.z,
                                   (v.w - mu) * inv * gg.w + bb.w);
    long base = (long)row * Dq + t * 4;
    *(__half2*)(o + base)     = p0;
    *(__half2*)(o + base + 2) = p1;
}

// ---------------------------------------------------------------------------
// Plain fp16 GEMM: C = A @ B.  Tile 128x128, BK=64, 8 warps (2x4),
// warp tile 64x32, 2-stage cp.async, 2 CTAs/SM, 1 barrier per K-step.
// EPI: 2 +bias+residual fp32; 3 +bias+relu -> fp16; 4 -> fp16 w/ q prescale
// ---------------------------------------------------------------------------
#define KPAD 72
#define AST (128 * KPAD)
#define BST (128 * KPAD)
#define STAGE (AST + BST)           // 18432 halves
#define GEMM_SMEM (2 * STAGE * 2)   // 73728 B

template <int EPI>
__global__ void __launch_bounds__(256, 2)
gemm_f16(const __half* __restrict__ A,
         const __half* __restrict__ B,
         const float* __restrict__ bias,
         const float* __restrict__ res,
         float* __restrict__ C,
         __half* __restrict__ Ch,
         int N, int K)
{
    extern __shared__ __half smem[];
    const int tid  = threadIdx.x;
    const int lane = tid & 31;
    const int warp = tid >> 5;
    const int wm = warp >> 2;          // 0..1 (64 rows)
    const int wn = warp & 3;           // 0..3 (32 cols)
    const int a_r = lane & 15;
    const int a_c = (lane >> 4) << 3;
    const int b_r = (lane & 7) + ((lane >> 4) << 3);
    const int b_c = ((lane >> 3) & 1) << 3;

    const int bm = blockIdx.y, bn = blockIdx.x;
    const __half* A_b = A + (long)bm * 128 * K;
    const __half* B_b = B + (long)bn * 128 * K;

    auto sA = [&](int st) -> __half* { return smem + st * STAGE; };
    auto sB = [&](int st) -> __half* { return smem + st * STAGE + AST; };

    auto ld_stage = [&](int st, int kt) {
        long k0 = (long)kt * 64;
        #pragma unroll
        for (int i = 0; i < 4; i++) {
            int c = tid + i * 256;
            int row = c >> 3, ch = (c & 7) * 8;
            cp16(sA(st) + row * KPAD + ch, A_b + (long)row * K + k0 + ch);
        }
        #pragma unroll
        for (int i = 0; i < 4; i++) {
            int c = tid + i * 256;
            int row = c >> 3, ch = (c & 7) * 8;
            cp16(sB(st) + row * KPAD + ch, B_b + (long)row * K + k0 + ch);
        }
    };

    float acc[4][4][4];
    #pragma unroll
    for (int i = 0; i < 4; i++)
        #pragma unroll
        for (int j = 0; j < 4; j++)
            #pragma unroll
            for (int r = 0; r < 4; r++) acc[i][j][r] = 0.f;

    const int KT = K / 64;
    ld_stage(0, 0); CP_COMMIT();

    for (int kt = 0; kt < KT; kt++) {
        CP_WAIT0();
        __syncthreads();
        if (kt + 1 < KT) {
            ld_stage((kt + 1) & 1, kt + 1);
            CP_COMMIT();
        }
        const __half* pA = sA(kt & 1);
        const __half* pB = sB(kt & 1);

        #pragma unroll
        for (int ks = 0; ks < 4; ks++) {
            const int k16 = ks * 16;
            uint32_t af[4][4], bf[4][2];
            #pragma unroll
            for (int mt = 0; mt < 4; mt++)
                ldmx4(af[mt], pA + (wm * 64 + mt * 16 + a_r) * KPAD + k16 + a_c);
            #pragma unroll
            for (int np = 0; np < 2; np++) {
                int row = wn * 32 + np * 16 + b_r;
                uint32_t r[4];
                ldmx4(r, pB + row * KPAD + k16 + b_c);
                bf[2*np][0] = r[0]; bf[2*np][1] = r[1];
                bf[2*np+1][0] = r[2]; bf[2*np+1][1] = r[3];
            }
            #pragma unroll
            for (int mt = 0; mt < 4; mt++)
                #pragma unroll
                for (int nt = 0; nt < 4; nt++)
                    mma_f16(acc[mt][nt], af[mt], bf[nt]);
        }
    }

    // epilogue
    const int lr4 = lane >> 2;
    const int lc2 = (lane & 3) * 2;
    #pragma unroll
    for (int mt = 0; mt < 4; mt++) {
        #pragma unroll
        for (int nt = 0; nt < 4; nt++) {
            int c = bn * 128 + wn * 32 + nt * 8 + lc2;
            #pragma unroll
            for (int half = 0; half < 2; half++) {
                int r = bm * 128 + wm * 64 + mt * 16 + lr4 + half * 8;
                float v0 = acc[mt][nt][half * 2 + 0];
                float v1 = acc[mt][nt][half * 2 + 1];
                long off = (long)r * N + c;
                if (EPI == 2) {
                    float2 bv = *(const float2*)(bias + c);
                    float2 rv = *(const float2*)(res + off);
                    *(float2*)(C + off) = make_float2(v0 + bv.x + rv.x,
                                                      v1 + bv.y + rv.y);
                } else if (EPI == 3) {
                    float2 bv = *(const float2*)(bias + c);
                    v0 = fmaxf(v0 + bv.x, 0.f);
                    v1 = fmaxf(v1 + bv.y, 0.f);
                    *(__half2*)(Ch + off) = __floats2half2_rn(v0, v1);
                } else {  // EPI == 4: fp16, q cols prescaled
                    float scale = (c < Dq) ? ATT_SCALE : 1.f;
                    *(__half2*)(Ch + off) = __floats2half2_rn(v0 * scale, v1 * scale);
                }
            }
        }
    }
}

// ---------------------------------------------------------------------------
// Flash attention, plain fp16, KV tile 64, double buffered, 2 CTAs/SM.
// Block: 128 Q rows x (b,h); 8 warps x 16 rows.
// ---------------------------------------------------------------------------
#define FPAD 72
#define FLASH_SMEM ((128 * FPAD + 2 * 2 * 64 * FPAD) * 2)   // 55296 B

__global__ void __launch_bounds__(256, 2)
flash_tc(const __half* __restrict__ qkv,
         __half* __restrict__ outp)
{
    extern __shared__ __half sm[];
    __half* QH = sm;

    const int qi  = gridDim.x - 1 - blockIdx.x;
    const int bh  = blockIdx.y;
    const int b   = bh >> 4;
    const int h   = bh & 15;
    const int tid  = threadIdx.x;
    const int lane = tid & 31;
    const int warp = tid >> 5;
    const int g  = lane >> 2;
    const int t2 = (lane & 3) * 2;
    const int a_r = lane & 15;
    const int a_c = (lane >> 4) << 3;
    const int b_r = (lane & 7) + ((lane >> 4) << 3);
    const int b_c = ((lane >> 3) & 1) << 3;

    const long rb = (long)b * Tq;
    const __half* qp = qkv + (rb + qi * 128) * (3 * Dq) + h * HDq;
    const __half* kp = qkv + rb * (3 * Dq) + Dq + h * HDq;
    const __half* vp = qkv + rb * (3 * Dq) + 2 * Dq + h * HDq;

    auto kvbase = [&](int st) -> __half* {
        return sm + 128 * FPAD + st * (2 * 64 * FPAD);
    };
    auto ldkv = [&](int st, int jt) {
        __half* KB = kvbase(st);
        #pragma unroll
        for (int i = 0; i < 2; i++) {
            int c = tid + i * 256;
            int row = c >> 3;
            int c8 = (c & 7) * 8;
            long go = (long)(jt * 64 + row) * (3 * Dq) + c8;
            int so = row * FPAD + c8;
            cp16(KB + so,             kp + go);
            cp16(KB + 64 * FPAD + so, vp + go);
        }
    };

    #pragma unroll
    for (int i = 0; i < 4; i++) {
        int c = tid + i * 256;
        int row = c >> 3;
        int c8 = (c & 7) * 8;
        cp16(QH + row * FPAD + c8, qp + (long)row * (3 * Dq) + c8);
    }
    ldkv(0, 0);
    CP_COMMIT();

    float oacc[8][4];
    #pragma unroll
    for (int nt = 0; nt < 8; nt++)
        #pragma unroll
        for (int e = 0; e < 4; e++) oacc[nt][e] = 0.f;
    float m0 = -1e30f, m1 = -1e30f, l0 = 0.f, l1 = 0.f;

    uint32_t qf[4][4];
    const int qrow0 = qi * 128 + warp * 16 + g;
    const int jmax = 2 * qi + 1;

    for (int jt = 0; jt <= jmax; jt++) {
        CP_WAIT0();
        __syncthreads();
        if (jt < jmax) { ldkv((jt + 1) & 1, jt + 1); CP_COMMIT(); }

        if (jt == 0) {
            #pragma unroll
            for (int kt = 0; kt < 4; kt++)
                ldmx4(qf[kt], QH + (warp * 16 + a_r) * FPAD + kt * 16 + a_c);
        }

        if (jt * 64 <= qi * 128 + warp * 16 + 15) {
            __half* KB = kvbase(jt & 1);
            const __half* KHs = KB;
            const __half* VHs = KB + 64 * FPAD;

            float sacc[8][4];
            #pragma unroll
            for (int nt = 0; nt < 8; nt++)
                #pragma unroll
                for (int e = 0; e < 4; e++) sacc[nt][e] = 0.f;

            #pragma unroll
            for (int kt = 0; kt < 4; kt++) {
                uint32_t bf[8][2];
                #pragma unroll
                for (int np = 0; np < 4; np++) {
                    int row = np * 16 + b_r;
                    uint32_t r[4];
                    ldmx4(r, KHs + row * FPAD + kt * 16 + b_c);
                    bf[2*np][0] = r[0]; bf[2*np][1] = r[1];
                    bf[2*np+1][0] = r[2]; bf[2*np+1][1] = r[3];
                }
                #pragma unroll
                for (int nt = 0; nt < 8; nt++)
                    mma_f16(sacc[nt], qf[kt], bf[nt]);
            }

            if (jt * 64 + 63 > qrow0) {
                #pragma unroll
                for (int nt = 0; nt < 8; nt++) {
                    int key0 = jt * 64 + nt * 8 + t2;
                    if (key0     > qrow0)     sacc[nt][0] = -1e30f;
                    if (key0 + 1 > qrow0)     sacc[nt][1] = -1e30f;
                    if (key0     > qrow0 + 8) sacc[nt][2] = -1e30f;
                    if (key0 + 1 > qrow0 + 8) sacc[nt][3] = -1e30f;
                }
            }

            float mx0 = -1e30f, mx1 = -1e30f;
            #pragma unroll
            for (int nt = 0; nt < 8; nt++) {
                mx0 = fmaxf(mx0, fmaxf(sacc[nt][0], sacc[nt][1]));
                mx1 = fmaxf(mx1, fmaxf(sacc[nt][2], sacc[nt][3]));
            }
            mx0 = fmaxf(mx0, __shfl_xor_sync(0xffffffffu, mx0, 1));
            mx0 = fmaxf(mx0, __shfl_xor_sync(0xffffffffu, mx0, 2));
            mx1 = fmaxf(mx1, __shfl_xor_sync(0xffffffffu, mx1, 1));
            mx1 = fmaxf(mx1, __shfl_xor_sync(0xffffffffu, mx1, 2));
            float mn0 = fmaxf(m0, mx0), mn1 = fmaxf(m1, mx1);
            float a0 = __expf(m0 - mn0), a1 = __expf(m1 - mn1);
            m0 = mn0; m1 = mn1;
            float rs0 = 0.f, rs1 = 0.f;
            #pragma unroll
            for (int nt = 0; nt < 8; nt++) {
                sacc[nt][0] = __expf(sacc[nt][0] - mn0); rs0 += sacc[nt][0];
                sacc[nt][1] = __expf(sacc[nt][1] - mn0); rs0 += sacc[nt][1];
                sacc[nt][2] = __expf(sacc[nt][2] - mn1); rs1 += sacc[nt][2];
                sacc[nt][3] = __expf(sacc[nt][3] - mn1); rs1 += sacc[nt][3];
            }
            rs0 += __shfl_xor_sync(0xffffffffu, rs0, 1);
            rs0 += __shfl_xor_sync(0xffffffffu, rs0, 2);
            rs1 += __shfl_xor_sync(0xffffffffu, rs1, 1);
            rs1 += __shfl_xor_sync(0xffffffffu, rs1, 2);
            l0 = l0 * a0 + rs0;
            l1 = l1 * a1 + rs1;
            #pragma unroll
            for (int nt = 0; nt < 8; nt++) {
                oacc[nt][0] *= a0; oacc[nt][1] *= a0;
                oacc[nt][2] *= a1; oacc[nt][3] *= a1;
            }

            #pragma unroll
            for (int j = 0; j < 4; j++) {
                uint32_t ph[4];
                ph[0] = packh2(sacc[2*j][0],   sacc[2*j][1]);
                ph[1] = packh2(sacc[2*j][2],   sacc[2*j][3]);
                ph[2] = packh2(sacc[2*j+1][0], sacc[2*j+1][1]);
                ph[3] = packh2(sacc[2*j+1][2], sacc[2*j+1][3]);
                #pragma unroll
                for (int nt = 0; nt < 8; nt++) {
                    uint32_t vf[2];
                    ldmx2t(vf[0], vf[1], VHs + (j * 16 + (lane & 15)) * FPAD + nt * 8);
                    mma_f16(oacc[nt], ph, vf);
                }
            }
        }
    }

    float inv0 = 1.f / l0, inv1 = 1.f / l1;
    long row0 = (long)b * Tq + qi * 128 + warp * 16 + g;
    #pragma unroll
    for (int nt = 0; nt < 8; nt++) {
        int col = h * HDq + nt * 8 + t2;
        *(__half2*)(outp + row0 * Dq + col) =
            __floats2half2_rn(oacc[nt][0] * inv0, oacc[nt][1] * inv0);
        *(__half2*)(outp + (row0 + 8) * Dq + col) =
            __floats2half2_rn(oacc[nt][2] * inv1, oacc[nt][3] * inv1);
    }
}

// ---------------------------------------------------------------------------
// Launch
// ---------------------------------------------------------------------------
extern "C" void kernel_launch(void* const* d_in, const int* in_sizes, int n_in,
                              void* d_out, int out_size)
{
    const float* x   = (const float*)d_in[0];
    const float* Wq  = (const float*)d_in[1];
    const float* Wk  = (const float*)d_in[2];
    const float* Wv  = (const float*)d_in[3];
    const float* Wp  = (const float*)d_in[4];
    const float* bp  = (const float*)d_in[5];
    const float* W1  = (const float*)d_in[6];
    const float* b1  = (const float*)d_in[7];
    const float* W2  = (const float*)d_in[8];
    const float* b2  = (const float*)d_in[9];
    const float* g1  = (const float*)d_in[10];
    const float* be1 = (const float*)d_in[11];
    const float* g2  = (const float*)d_in[12];
    const float* be2 = (const float*)d_in[13];
    float* out = (float*)d_out;

    __half *p_h, *p_wqkv, *p_wp, *p_w1, *p_w2, *p_attn, *p_ff, *p_qkv;
    float *p_x1;
    cudaGetSymbolAddress((void**)&p_h,    g_h);
    cudaGetSymbolAddress((void**)&p_wqkv, g_wqkv);
    cudaGetSymbolAddress((void**)&p_wp,   g_wp);
    cudaGetSymbolAddress((void**)&p_w1,   g_w1);
    cudaGetSymbolAddress((void**)&p_w2,   g_w2);
    cudaGetSymbolAddress((void**)&p_qkv,  g_qkv);
    cudaGetSymbolAddress((void**)&p_attn, g_attn);
    cudaGetSymbolAddress((void**)&p_x1,   g_x1);
    cudaGetSymbolAddress((void**)&p_ff,   g_ff);

    cudaFuncSetAttribute(gemm_f16<2>, cudaFuncAttributeMaxDynamicSharedMemorySize, GEMM_SMEM);
    cudaFuncSetAttribute(gemm_f16<3>, cudaFuncAttributeMaxDynamicSharedMemorySize, GEMM_SMEM);
    cudaFuncSetAttribute(gemm_f16<4>, cudaFuncAttributeMaxDynamicSharedMemorySize, GEMM_SMEM);
    cudaFuncSetAttribute(flash_tc,    cudaFuncAttributeMaxDynamicSharedMemorySize, FLASH_SMEM);

    // merged weight prep
    prep_all<<<12288, dim3(32, 8)>>>(Wq, Wk, Wv, Wp, W1, W2,
                                     p_wqkv, p_wp, p_w1, p_w2);

    // LN1 -> fp16
    ln_f16<<<Mq, 256>>>(x, g1, be1, p_h);
    // QKV projection -> fp16, q prescaled
    gemm_f16<4><<<dim3(3 * Dq / 128, Mq / 128), 256, GEMM_SMEM>>>(
        p_h, p_wqkv, nullptr, nullptr, nullptr, p_qkv, 3 * Dq, Dq);
    // flash attention -> fp16
    flash_tc<<<dim3(Tq / 128, Bq * Hq), 256, FLASH_SMEM>>>(p_qkv, p_attn);
    // output projection + bias + residual(x)
    gemm_f16<2><<<dim3(Dq / 128, Mq / 128), 256, GEMM_SMEM>>>(
        p_attn, p_wp, bp, x, p_x1, nullptr, Dq, Dq);
    // LN2 -> fp16
    ln_f16<<<Mq, 256>>>(p_x1, g2, be2, p_h);
    // FFN up + bias + relu -> fp16
    gemm_f16<3><<<dim3(DFF / 128, Mq / 128), 256, GEMM_SMEM>>>(
        p_h, p_w1, b1, nullptr, nullptr, p_ff, DFF, Dq);
    // FFN down + bias + residual(x1) -> d_out
    gemm_f16<2><<<dim3(Dq / 128, Mq / 128), 256, GEMM_SMEM>>>(
        p_ff, p_w2, b2, p_x1, out, nullptr, Dq, DFF);
}